// round 13
// baseline (speedup 1.0000x reference)
#include <cuda_runtime.h>
#include <cuda_bf16.h>
#include <math.h>

#define NV   65536
#define CH   128
#define NSEGS 1024
#define KT   27
#define NC   (NV*CH)

typedef unsigned long long u64;
typedef unsigned int u32;

__device__ __forceinline__ float lrelu(float v) { return v >= 0.f ? v : 0.01f * v; }
__device__ __forceinline__ u32 enc_max(float f) {
    u32 u = __float_as_uint(f);
    return (u & 0x80000000u) ? ~u : (u | 0x80000000u);
}
__device__ __forceinline__ float dec_max(u32 k) {
    u32 u = (k & 0x80000000u) ? (k & 0x7FFFFFFFu) : ~k;
    return __uint_as_float(u);
}

// ---------------- scratch ----------------------------------------------------
__device__ float g_pw3[3*NC];
__device__ float g_t3[3*NC];
__device__ float g_pf4[4*NC];
__device__ float g_tf[NC];
__device__ float g_agg[NC];
__device__ float g_fused[NC];
__device__ float g_ybuf[NC];
__device__ float g_dbuf[NC];
__device__ float g_adp[NV*3];
__device__ float g_seg3[3*NSEGS*CH];
__device__ float g_segE[3*NSEGS*CH];
__device__ float g_seg2[3*NSEGS*CH];
__device__ float g_cnt3[3*NSEGS];
__device__ float g_sum8[8*CH];
__device__ float g_sumq8[8*CH];
__device__ float g_scale8[8*CH];
__device__ float g_bias8[8*CH];
__device__ u32   g_gmax3[3];
__device__ __align__(256) __nv_bfloat16 g_wimg[2*KT*32768];
__device__ __align__(256) __nv_bfloat16 g_dwimg[12*32768];
__device__ __align__(256) __nv_bfloat16 g_xhi[NC];
__device__ __align__(256) __nv_bfloat16 g_xlo[NC];

// ======================= shared HMMA helpers ==================================
#define ROWB 272
#define T128 (128*ROWB)               // 34816
#define T64  (64*ROWB)                // 17408
// dense gemm (64x64): A_HI(T64) A_LO(T64) W_HI(T64) W_LO(T64)
#define G2_ALO  T64
#define G2_WHI  (2*T64)
#define G2_WLO  (3*T64)
#define GSMEM2  (4*T64)               // 69632 -> 3 CTAs/SM
// sconv (128x64, A+W double buffered):
#define SC_AB0  0
#define SC_AB1  (2*T128)
#define SC_WB0  (4*T128)
#define SC_WB1  (4*T128 + 2*T64)
#define SSMEM   (4*T128 + 4*T64)      // 208896 -> 1 CTA/SM

__device__ __forceinline__ u32 smem_u32(const void* p) {
    u32 a; asm("{ .reg .u64 t; cvta.to.shared.u64 t, %1; cvt.u32.u64 %0, t; }"
               : "=r"(a) : "l"(p));
    return a;
}
__device__ __forceinline__ void cp16(u32 dst, const void* src, u32 srcsz) {
    asm volatile("cp.async.cg.shared.global [%0], [%1], 16, %2;"
                 :: "r"(dst), "l"(src), "r"(srcsz) : "memory");
}
__device__ __forceinline__ void ldm4(u32 addr, u32& r0, u32& r1, u32& r2, u32& r3) {
    asm volatile("ldmatrix.sync.aligned.m8n8.x4.shared.b16 {%0,%1,%2,%3}, [%4];"
                 : "=r"(r0), "=r"(r1), "=r"(r2), "=r"(r3) : "r"(addr));
}
__device__ __forceinline__ void mma16816(float* c, const u32* a, const u32* b) {
    asm volatile(
        "mma.sync.aligned.m16n8k16.row.col.f32.bf16.bf16.f32 "
        "{%0,%1,%2,%3}, {%4,%5,%6,%7}, {%8,%9}, {%0,%1,%2,%3};"
        : "+f"(c[0]), "+f"(c[1]), "+f"(c[2]), "+f"(c[3])
        : "r"(a[0]), "r"(a[1]), "r"(a[2]), "r"(a[3]), "r"(b[0]), "r"(b[1]));
}

template<int NT>
__device__ __forceinline__ void mma_ld(u32 aHi, u32 aLo, u32 wHi, u32 wLo,
                                       float acc[2][NT][4], int mwarp, int nwarp, int lane)
{
    const int r = lane & 7, j = lane >> 3;
    const u32 aoff = (u32)(mwarp + (j & 1) * 8 + r) * ROWB + (u32)(j >> 1) * 16u;
    const u32 boff = (u32)(nwarp + (j >> 1) * 8 + r) * ROWB + (u32)(j & 1) * 16u;
#pragma unroll
    for (int kc = 0; kc < 8; kc++) {
        u32 ah[2][4], al[2][4];
#pragma unroll
        for (int mt = 0; mt < 2; mt++) {
            u32 adr = aoff + (u32)mt * (16u * ROWB) + (u32)kc * 32u;
            ldm4(aHi + adr, ah[mt][0], ah[mt][1], ah[mt][2], ah[mt][3]);
            ldm4(aLo + adr, al[mt][0], al[mt][1], al[mt][2], al[mt][3]);
        }
        u32 bh[NT][2], bl[NT][2];
#pragma unroll
        for (int np = 0; np < NT / 2; np++) {
            u32 bdr = boff + (u32)np * (16u * ROWB) + (u32)kc * 32u;
            ldm4(wHi + bdr, bh[2*np][0], bh[2*np][1], bh[2*np+1][0], bh[2*np+1][1]);
            ldm4(wLo + bdr, bl[2*np][0], bl[2*np][1], bl[2*np+1][0], bl[2*np+1][1]);
        }
#pragma unroll
        for (int mt = 0; mt < 2; mt++)
#pragma unroll
            for (int nt = 0; nt < NT; nt++) {
                mma16816(acc[mt][nt], ah[mt], bh[nt]);
                mma16816(acc[mt][nt], al[mt], bh[nt]);
                mma16816(acc[mt][nt], ah[mt], bl[nt]);
            }
    }
}

// ---------------- weight prep -------------------------------------------------
__global__ void wprep(const float* __restrict__ W1, const float* __restrict__ W2,
                      __nv_bfloat16* __restrict__ img)
{
    int b = blockIdx.x;
    const float* W = (b < KT ? W1 : W2) + (size_t)(b % KT) * CH * CH;
    __nv_bfloat16* o = img + (size_t)b * 32768;
    for (int u = threadIdx.x; u < 16384; u += blockDim.x) {
        int cout = u >> 7, cin = u & 127;
        float v = W[cin * CH + cout];
        __nv_bfloat16 h = __float2bfloat16(v);
        o[u]         = h;
        o[16384 + u] = __float2bfloat16(v - __bfloat162float(h));
    }
}

__global__ void dwprep(const float* __restrict__ lw, const float* __restrict__ ww,
                       const float* __restrict__ pj, const float* __restrict__ fw,
                       __nv_bfloat16* __restrict__ img)
{
    int b = blockIdx.x;
    const float* W;
    if (b < 3)       W = lw + (size_t)b * 16384;
    else if (b < 6)  W = ww + (size_t)(b - 3) * 16384;
    else if (b < 10) W = pj + (size_t)(b - 6) * 16384;
    else             W = fw + (size_t)(b - 10) * 16384;
    __nv_bfloat16* o = img + (size_t)b * 32768;
    for (int u = threadIdx.x; u < 16384; u += blockDim.x) {
        int n = u >> 7, k = u & 127;
        float v = W[k * CH + n];
        __nv_bfloat16 h = __float2bfloat16(v);
        o[u]         = h;
        o[16384 + u] = __float2bfloat16(v - __bfloat162float(h));
    }
}

// ======================= HMMA dense GEMM (64x64 tiles, 3 CTA/SM) ==============
template<int PRO, int EPI, int ACC>
__global__ __launch_bounds__(256, 3)
void gemm_mma(const float* __restrict__ A, const __nv_bfloat16* __restrict__ Wimg,
              float* __restrict__ Cc,
              const float* __restrict__ scp, const float* __restrict__ sbp,
              float* __restrict__ sumP, float* __restrict__ sumqP,
              u32* __restrict__ gmaxP)
{
    extern __shared__ char dsm[];
    const u32 sb = smem_u32(dsm);
    __shared__ float s_sc[128], s_sb[128];

    const int tid = threadIdx.x;
    const int wid = tid >> 5, lane = tid & 31;
    const int g = lane >> 2, tg = lane & 3;
    const int wm = wid & 1, wn = wid >> 1;
    const int brow = (blockIdx.x >> 1) * 64;
    const int bcol = (blockIdx.x & 1) * 64;

    {
        const int wr = tid >> 2, wq = tid & 3;
        u32 wdst = sb + G2_WHI + (u32)wr * ROWB + (u32)wq * 64;
        const char* whi = (const char*)(Wimg + (size_t)(bcol + wr) * 128) + wq * 64;
#pragma unroll
        for (int j = 0; j < 4; j++) {
            cp16(wdst + j * 16,       whi + j * 16, 16u);
            cp16(wdst + T64 + j * 16, whi + 32768 + j * 16, 16u);
        }
        asm volatile("cp.async.commit_group;" ::: "memory");
    }
    if (PRO && tid < 128) { s_sc[tid] = scp[tid]; s_sb[tid] = sbp[tid]; }

    const int ar = tid >> 2, aq = tid & 3;
    float4 av[8];
    {
        const float4* Ap = (const float4*)(A + (size_t)(brow + ar) * CH + aq * 32);
#pragma unroll
        for (int j = 0; j < 8; j++) av[j] = Ap[j];
    }
    __syncthreads();

    {
        u64* hp = (u64*)(dsm + (u32)ar * ROWB + (u32)aq * 64);
        u64* lp = (u64*)(dsm + G2_ALO + (u32)ar * ROWB + (u32)aq * 64);
#pragma unroll
        for (int j = 0; j < 8; j++) {
            float4 v = av[j];
            if (PRO) {
                int cb = aq * 32 + j * 4;
                v.x = lrelu(v.x * s_sc[cb]     + s_sb[cb]);
                v.y = lrelu(v.y * s_sc[cb + 1] + s_sb[cb + 1]);
                v.z = lrelu(v.z * s_sc[cb + 2] + s_sb[cb + 2]);
                v.w = lrelu(v.w * s_sc[cb + 3] + s_sb[cb + 3]);
            }
            __nv_bfloat162 h01 = __floats2bfloat162_rn(v.x, v.y);
            __nv_bfloat162 h23 = __floats2bfloat162_rn(v.z, v.w);
            float2 f01 = __bfloat1622float2(h01);
            float2 f23 = __bfloat1622float2(h23);
            __nv_bfloat162 l01 = __floats2bfloat162_rn(v.x - f01.x, v.y - f01.y);
            __nv_bfloat162 l23 = __floats2bfloat162_rn(v.z - f23.x, v.w - f23.y);
            hp[j] = ((u64)(*(u32*)&h23) << 32) | (u64)(*(u32*)&h01);
            lp[j] = ((u64)(*(u32*)&l23) << 32) | (u64)(*(u32*)&l01);
        }
    }
    asm volatile("cp.async.wait_group 0;" ::: "memory");
    __syncthreads();

    float acc[2][2][4];
#pragma unroll
    for (int mt = 0; mt < 2; mt++)
#pragma unroll
        for (int nt = 0; nt < 2; nt++)
#pragma unroll
            for (int q = 0; q < 4; q++) acc[mt][nt][q] = 0.f;

    mma_ld<2>(sb, sb + G2_ALO, sb + G2_WHI, sb + G2_WLO, acc, wm * 32, wn * 16, lane);

    float colS[2][2], colQ[2][2];
    if (EPI == 1) {
#pragma unroll
        for (int nt = 0; nt < 2; nt++) { colS[nt][0] = colS[nt][1] = 0.f;
                                         colQ[nt][0] = colQ[nt][1] = 0.f; }
    }
    float bmax = -3.4e38f;

#pragma unroll
    for (int mt = 0; mt < 2; mt++) {
        int row0 = brow + wm * 32 + mt * 16 + g;
#pragma unroll
        for (int nt = 0; nt < 2; nt++) {
            int col = bcol + wn * 16 + nt * 8 + tg * 2;
            float* p0 = Cc + (size_t)row0 * CH + col;
            float* p1 = Cc + (size_t)(row0 + 8) * CH + col;
            float c0 = acc[mt][nt][0], c1 = acc[mt][nt][1];
            float c2 = acc[mt][nt][2], c3 = acc[mt][nt][3];
            if (ACC) {
                float2 o0 = *(float2*)p0, o1 = *(float2*)p1;
                c0 += o0.x; c1 += o0.y; c2 += o1.x; c3 += o1.y;
            }
            if (EPI == 1) {
                colS[nt][0] += c0 + c2; colS[nt][1] += c1 + c3;
                colQ[nt][0] += c0 * c0 + c2 * c2; colQ[nt][1] += c1 * c1 + c3 * c3;
            }
            if (EPI == 2) bmax = fmaxf(bmax, fmaxf(fmaxf(c0, c1), fmaxf(c2, c3)));
            *(float2*)p0 = make_float2(c0, c1);
            *(float2*)p1 = make_float2(c2, c3);
        }
    }

    if (EPI == 1) {
        __syncthreads();
        float* red = (float*)dsm;
        if (tid < 128) red[tid] = 0.f;
        __syncthreads();
#pragma unroll
        for (int nt = 0; nt < 2; nt++) {
            int lc = wn * 16 + nt * 8 + tg * 2;
            atomicAdd(&red[lc],          colS[nt][0]);
            atomicAdd(&red[lc + 1],      colS[nt][1]);
            atomicAdd(&red[64 + lc],     colQ[nt][0]);
            atomicAdd(&red[64 + lc + 1], colQ[nt][1]);
        }
        __syncthreads();
        if (tid < 64) {
            atomicAdd(&sumP[bcol + tid],  red[tid]);
            atomicAdd(&sumqP[bcol + tid], red[64 + tid]);
        }
    }
    if (EPI == 2) {
#pragma unroll
        for (int o = 16; o; o >>= 1)
            bmax = fmaxf(bmax, __shfl_xor_sync(0xffffffffu, bmax, o));
        if (lane == 0) atomicMax(gmaxP, enc_max(bmax));
    }
}

// ========== HMMA sparse conv (128x64 tiles, A+W double-buffered pipeline) =====
__global__ __launch_bounds__(256, 1)
void sconv_mma(const __nv_bfloat16* __restrict__ Xhi,
               const __nv_bfloat16* __restrict__ Xlo,
               const int* __restrict__ nbr,
               const __nv_bfloat16* __restrict__ Wimg,
               float* __restrict__ Out,
               float* __restrict__ sumP, float* __restrict__ sumqP)
{
    extern __shared__ char dsm[];
    const u32 sb = smem_u32(dsm);

    const int tid = threadIdx.x;
    const int wid = tid >> 5, lane = tid & 31;
    const int g = lane >> 2, tg = lane & 3;
    const int wm = wid & 3, wn = wid >> 2;          // 4x2 warps over 128x64
    const int brow = (blockIdx.x >> 1) * 128;
    const int bcol = (blockIdx.x & 1) * 64;
    const int cr = tid >> 1, chalf = tid & 1;       // A: 128 rows, 2 thr/row
    const int wr = tid >> 2, wq = tid & 3;          // W: 64 rows, 4 thr/row
    const u32 arow = (u32)cr * ROWB + (u32)chalf * 128;
    const u32 wrow = (u32)wr * ROWB + (u32)wq * 64;
    const size_t nbase = (size_t)(brow + cr) * KT;

    float acc[2][4][4];
#pragma unroll
    for (int mt = 0; mt < 2; mt++)
#pragma unroll
        for (int nt = 0; nt < 4; nt++)
#pragma unroll
            for (int q = 0; q < 4; q++) acc[mt][nt][q] = 0.f;

    auto issue_tap = [&](int k, u32 ab, u32 wb) {
        int n = nbr[nbase + k];
        bool valid = n < NV;
        u32 sz = valid ? 16u : 0u;
        const char* shi = (const char*)(Xhi + (size_t)(valid ? n : 0) * CH) + chalf * 128;
        const char* slo = (const char*)(Xlo + (size_t)(valid ? n : 0) * CH) + chalf * 128;
#pragma unroll
        for (int j = 0; j < 8; j++) {
            cp16(ab + arow + j * 16,        shi + j * 16, sz);
            cp16(ab + T128 + arow + j * 16, slo + j * 16, sz);
        }
        const char* whi = (const char*)(Wimg + (size_t)k * 32768)
                        + (size_t)(bcol + wr) * 256 + wq * 64;
#pragma unroll
        for (int j = 0; j < 4; j++) {
            cp16(wb + wrow + j * 16,       whi + j * 16, 16u);
            cp16(wb + T64 + wrow + j * 16, whi + 32768 + j * 16, 16u);
        }
        asm volatile("cp.async.commit_group;" ::: "memory");
    };

    issue_tap(0, sb + SC_AB0, sb + SC_WB0);

#pragma unroll 1
    for (int k = 0; k < KT; k++) {
        const u32 ab = sb + ((k & 1) ? SC_AB1 : SC_AB0);
        const u32 wb = sb + ((k & 1) ? SC_WB1 : SC_WB0);
        if (k < KT - 1) {
            issue_tap(k + 1, sb + ((k & 1) ? SC_AB0 : SC_AB1),
                             sb + ((k & 1) ? SC_WB0 : SC_WB1));
            asm volatile("cp.async.wait_group 1;" ::: "memory");   // tap k landed
        } else {
            asm volatile("cp.async.wait_group 0;" ::: "memory");
        }
        __syncthreads();

        mma_ld<4>(ab, ab + T128, wb, wb + T64, acc, wm * 32, wn * 32, lane);
        __syncthreads();   // alt buffers drained before next issue
    }

    float colS[4][2], colQ[4][2];
#pragma unroll
    for (int nt = 0; nt < 4; nt++) { colS[nt][0] = colS[nt][1] = 0.f;
                                     colQ[nt][0] = colQ[nt][1] = 0.f; }
#pragma unroll
    for (int mt = 0; mt < 2; mt++) {
        int row0 = brow + wm * 32 + mt * 16 + g;
#pragma unroll
        for (int nt = 0; nt < 4; nt++) {
            int col = bcol + wn * 32 + nt * 8 + tg * 2;
            float c0 = acc[mt][nt][0], c1 = acc[mt][nt][1];
            float c2 = acc[mt][nt][2], c3 = acc[mt][nt][3];
            colS[nt][0] += c0 + c2; colS[nt][1] += c1 + c3;
            colQ[nt][0] += c0 * c0 + c2 * c2; colQ[nt][1] += c1 * c1 + c3 * c3;
            *(float2*)(Out + (size_t)row0 * CH + col)       = make_float2(c0, c1);
            *(float2*)(Out + (size_t)(row0 + 8) * CH + col) = make_float2(c2, c3);
        }
    }
    __syncthreads();
    float* red = (float*)dsm;        // 64 sum + 64 sumsq (local cols)
    if (tid < 128) red[tid] = 0.f;
    __syncthreads();
#pragma unroll
    for (int nt = 0; nt < 4; nt++) {
        int lc = wn * 32 + nt * 8 + tg * 2;
        atomicAdd(&red[lc],          colS[nt][0]);
        atomicAdd(&red[lc + 1],      colS[nt][1]);
        atomicAdd(&red[64 + lc],     colQ[nt][0]);
        atomicAdd(&red[64 + lc + 1], colQ[nt][1]);
    }
    __syncthreads();
    if (tid < 64) {
        atomicAdd(&sumP[bcol + tid],  red[tid]);
        atomicAdd(&sumqP[bcol + tid], red[64 + tid]);
    }
}

// ---------------- BN finalize (self-zeroing) ----------------------------------
__global__ void bn_finalize(float* __restrict__ sum, float* __restrict__ sumsq,
                            const float* __restrict__ gamma, const float* __restrict__ beta,
                            float* __restrict__ scale, float* __restrict__ bias)
{
    int c = threadIdx.x;
    float s = sum[c], q = sumsq[c];
    sum[c] = 0.f; sumsq[c] = 0.f;
    float m = s * (1.f / (float)NV);
    float v = q * (1.f / (float)NV) - m * m;
    float sc = gamma[c] * rsqrtf(v + 1e-5f);
    scale[c] = sc;
    bias[c] = beta[c] - m * sc;
}

// ---------------- elementwise / segment kernels -------------------------------
__global__ void seg_count(const int* __restrict__ cl, float* __restrict__ cnt)
{
    int i = blockIdx.x * blockDim.x + threadIdx.x;
    atomicAdd(&cnt[cl[i]], 1.f);
}

// read-only on X: seg += lrelu(bn(X))
__global__ void seg_sum_bn(const float* __restrict__ X, const float* __restrict__ sc,
                           const float* __restrict__ sb, const int* __restrict__ cl,
                           float* __restrict__ S)
{
    int i = blockIdx.x * blockDim.x + threadIdx.x;
    int n = i >> 7, c = i & 127;
    float v = lrelu(X[i] * sc[c] + sb[c]);
    atomicAdd(&S[(size_t)cl[n] * CH + c], v);
}

// X <- lrelu(bn(X)) - segmean  (recomputes bn+lrelu)
__global__ void sub_segmean(float* __restrict__ X, const float* __restrict__ sc,
                            const float* __restrict__ sb, const float* __restrict__ S,
                            const float* __restrict__ cnt, const int* __restrict__ cl)
{
    int i = blockIdx.x * blockDim.x + threadIdx.x;
    int n = i >> 7, c = i & 127;
    int s = cl[n];
    float v = lrelu(X[i] * sc[c] + sb[c]);
    X[i] = v - S[(size_t)s * CH + c] / fmaxf(cnt[s], 1.f);
}

__global__ void exp_seg(const float* __restrict__ T, const u32* __restrict__ gmaxP,
                        const int* __restrict__ cl, float* __restrict__ S)
{
    int i = blockIdx.x * blockDim.x + threadIdx.x;
    int n = i >> 7, c = i & 127;
    float e = expf(T[i] - dec_max(*gmaxP));
    atomicAdd(&S[(size_t)cl[n] * CH + c], e);
}

__global__ void wmul_seg_bn(const float* __restrict__ PF, const float* __restrict__ sc,
                            const float* __restrict__ sb, const float* __restrict__ T,
                            const u32* __restrict__ gmaxP, const float* __restrict__ S,
                            const int* __restrict__ cl, float* __restrict__ S2)
{
    int i = blockIdx.x * blockDim.x + threadIdx.x;
    int n = i >> 7, c = i & 127;
    int s = cl[n];
    float pfv = lrelu(PF[i] * sc[c] + sb[c]);
    float e = expf(T[i] - dec_max(*gmaxP));
    float v = pfv * (e / (S[(size_t)s * CH + c] + 1e-6f));
    atomicAdd(&S2[(size_t)s * CH + c], v);
}

__global__ void agg_k(const float* __restrict__ adp, const int* __restrict__ clusters,
                      const float* __restrict__ S2, float* __restrict__ AGG)
{
    int i = blockIdx.x * blockDim.x + threadIdx.x;
    int n = i >> 7, c = i & 127;
    float r = 0.f;
#pragma unroll
    for (int lvl = 0; lvl < 3; lvl++) {
        int s = clusters[(size_t)lvl * NV + n];
        r += adp[n * 3 + lvl] * S2[(size_t)lvl * NSEGS * CH + (size_t)s * CH + c];
    }
    AGG[i] = r;
}

__global__ void bnact_hilo(const float* __restrict__ X, const float* __restrict__ scale,
                           const float* __restrict__ bias,
                           __nv_bfloat16* __restrict__ Hi, __nv_bfloat16* __restrict__ Lo)
{
    int i = blockIdx.x * blockDim.x + threadIdx.x;
    int c = i & 127;
    float v = lrelu(X[i] * scale[c] + bias[c]);
    __nv_bfloat16 h = __float2bfloat16(v);
    Hi[i] = h;
    Lo[i] = __float2bfloat16(v - __bfloat162float(h));
}

__global__ void fusedres_hilo(const float* __restrict__ T, const float* __restrict__ sc,
                              const float* __restrict__ sb, const float* __restrict__ feat,
                              float* __restrict__ F,
                              __nv_bfloat16* __restrict__ Hi, __nv_bfloat16* __restrict__ Lo)
{
    int i = blockIdx.x * blockDim.x + threadIdx.x;
    int c = i & 127;
    float v = lrelu(T[i] * sc[c] + sb[c]) + feat[i];
    F[i] = v;
    __nv_bfloat16 h = __float2bfloat16(v);
    Hi[i] = h;
    Lo[i] = __float2bfloat16(v - __bfloat162float(h));
}

__global__ void final_k(const float* __restrict__ D, const float* __restrict__ sc,
                        const float* __restrict__ sb, const float* __restrict__ F,
                        float* __restrict__ O)
{
    int i = blockIdx.x * blockDim.x + threadIdx.x;
    int c = i & 127;
    O[i] = lrelu(D[i] * sc[c] + sb[c] + F[i]);
}

// ---------------- adaptive softmax -------------------------------------------
__global__ void adp_kernel(const float* __restrict__ feat, const float* __restrict__ aw,
                           float* __restrict__ adp)
{
    int row = blockIdx.x * 8 + (threadIdx.x >> 5);
    int lane = threadIdx.x & 31;
    float d0 = 0.f, d1 = 0.f, d2 = 0.f;
    const float* f = feat + (size_t)row * CH;
#pragma unroll
    for (int j = lane; j < CH; j += 32) {
        float v = f[j];
        d0 += v * aw[j * 3 + 0];
        d1 += v * aw[j * 3 + 1];
        d2 += v * aw[j * 3 + 2];
    }
#pragma unroll
    for (int o = 16; o; o >>= 1) {
        d0 += __shfl_xor_sync(0xffffffffu, d0, o);
        d1 += __shfl_xor_sync(0xffffffffu, d1, o);
        d2 += __shfl_xor_sync(0xffffffffu, d2, o);
    }
    if (lane == 0) {
        float m = fmaxf(d0, fmaxf(d1, d2));
        float e0 = expf(d0 - m), e1 = expf(d1 - m), e2 = expf(d2 - m);
        float inv = 1.f / (e0 + e1 + e2);
        adp[row * 3 + 0] = e0 * inv;
        adp[row * 3 + 1] = e1 * inv;
        adp[row * 3 + 2] = e2 * inv;
    }
}

// ---------------- orchestration ----------------------------------------------
extern "C" void kernel_launch(void* const* d_in, const int* in_sizes, int n_in,
                              void* d_out, int out_size)
{
    const float* feat       = (const float*)d_in[0];
    const int*   clusters   = (const int*)d_in[1];
    const int*   nbr        = (const int*)d_in[2];
    const float* lw_w       = (const float*)d_in[3];
    const float* lw_gamma   = (const float*)d_in[4];
    const float* lw_beta    = (const float*)d_in[5];
    const float* w_w        = (const float*)d_in[6];
    const float* proj_w     = (const float*)d_in[7];
    const float* proj_gamma = (const float*)d_in[8];
    const float* proj_beta  = (const float*)d_in[9];
    const float* adaptive_w = (const float*)d_in[10];
    const float* fuse_w     = (const float*)d_in[11];
    const float* fuse_gamma = (const float*)d_in[12];
    const float* fuse_beta  = (const float*)d_in[13];
    const float* conv1_w    = (const float*)d_in[14];
    const float* conv2_w    = (const float*)d_in[15];
    const float* bn1_gamma  = (const float*)d_in[16];
    const float* bn1_beta   = (const float*)d_in[17];
    const float* bn2_gamma  = (const float*)d_in[18];
    const float* bn2_beta   = (const float*)d_in[19];
    float* out = (float*)d_out;

    float *pw3, *t3, *pf4, *tf, *agg, *fused, *ybuf, *dbuf, *adp;
    float *seg3, *segE, *seg2, *cnt3, *sum8, *sumq8, *scale8, *bias8;
    u32 *gmax3;
    __nv_bfloat16 *wimg, *dwimg, *xhi, *xlo;
    cudaGetSymbolAddress((void**)&pw3, g_pw3);
    cudaGetSymbolAddress((void**)&t3, g_t3);
    cudaGetSymbolAddress((void**)&pf4, g_pf4);
    cudaGetSymbolAddress((void**)&tf, g_tf);
    cudaGetSymbolAddress((void**)&agg, g_agg);
    cudaGetSymbolAddress((void**)&fused, g_fused);
    cudaGetSymbolAddress((void**)&ybuf, g_ybuf);
    cudaGetSymbolAddress((void**)&dbuf, g_dbuf);
    cudaGetSymbolAddress((void**)&adp, g_adp);
    cudaGetSymbolAddress((void**)&seg3, g_seg3);
    cudaGetSymbolAddress((void**)&segE, g_segE);
    cudaGetSymbolAddress((void**)&seg2, g_seg2);
    cudaGetSymbolAddress((void**)&cnt3, g_cnt3);
    cudaGetSymbolAddress((void**)&sum8, g_sum8);
    cudaGetSymbolAddress((void**)&sumq8, g_sumq8);
    cudaGetSymbolAddress((void**)&scale8, g_scale8);
    cudaGetSymbolAddress((void**)&bias8, g_bias8);
    cudaGetSymbolAddress((void**)&gmax3, g_gmax3);
    cudaGetSymbolAddress((void**)&wimg, g_wimg);
    cudaGetSymbolAddress((void**)&dwimg, g_dwimg);
    cudaGetSymbolAddress((void**)&xhi, g_xhi);
    cudaGetSymbolAddress((void**)&xlo, g_xlo);

    cudaFuncSetAttribute(sconv_mma, cudaFuncAttributeMaxDynamicSharedMemorySize, SSMEM);
    cudaFuncSetAttribute(gemm_mma<0,1,0>, cudaFuncAttributeMaxDynamicSharedMemorySize, GSMEM2);
    cudaFuncSetAttribute(gemm_mma<0,2,0>, cudaFuncAttributeMaxDynamicSharedMemorySize, GSMEM2);
    cudaFuncSetAttribute(gemm_mma<1,0,0>, cudaFuncAttributeMaxDynamicSharedMemorySize, GSMEM2);
    cudaFuncSetAttribute(gemm_mma<0,1,1>, cudaFuncAttributeMaxDynamicSharedMemorySize, GSMEM2);

    static cudaStream_t st[3];
    static cudaEvent_t evR, evJ[3];
    static int inited = 0;
    if (!inited) {
        for (int k = 0; k < 3; k++)
            cudaStreamCreateWithFlags(&st[k], cudaStreamNonBlocking);
        cudaEventCreateWithFlags(&evR, cudaEventDisableTiming);
        for (int k = 0; k < 3; k++)
            cudaEventCreateWithFlags(&evJ[k], cudaEventDisableTiming);
        inited = 1;
    }

    const int EB = 256;
    const int EG = NC / EB;
    const int GG2 = (NV / 64) * 2;   // 2048 (64x64 gemm tiles)
    const int SG2 = (NV / 128) * 2;  // 1024 (128x64 sconv tiles)

    // ---- prologue ----
    wprep<<<2 * KT, 256>>>(conv1_w, conv2_w, wimg);
    dwprep<<<12, 256>>>(lw_w, w_w, proj_w, fuse_w, dwimg);
    adp_kernel<<<NV / 8, 256>>>(feat, adaptive_w, adp);

    // ---- fork ----
    cudaEventRecord(evR, 0);
    for (int k = 0; k < 3; k++) cudaStreamWaitEvent(st[k], evR, 0);

    auto level_chain = [&](int i, cudaStream_t s) {
        const int* cl = clusters + (size_t)i * NV;
        float* pw = pw3 + (size_t)i * NC;
        float* t  = t3  + (size_t)i * NC;
        float* pf = pf4 + (size_t)i * NC;
        float* seg  = seg3 + (size_t)i * NSEGS * CH;
        float* sgE  = segE + (size_t)i * NSEGS * CH;
        float* sg2  = seg2 + (size_t)i * NSEGS * CH;
        float* cnt  = cnt3 + (size_t)i * NSEGS;
        float* sum  = sum8 + i * CH;
        float* sumq = sumq8 + i * CH;
        float* sc   = scale8 + i * CH;
        float* sb   = bias8 + i * CH;
        u32* gm = gmax3 + i;

        cudaMemsetAsync(cnt, 0, NSEGS * sizeof(float), s);
        cudaMemsetAsync(seg, 0, (size_t)NSEGS * CH * sizeof(float), s);
        cudaMemsetAsync(sgE, 0, (size_t)NSEGS * CH * sizeof(float), s);
        cudaMemsetAsync(sg2, 0, (size_t)NSEGS * CH * sizeof(float), s);
        cudaMemsetAsync(gm, 0, sizeof(u32), s);
        seg_count<<<NV / 256, 256, 0, s>>>(cl, cnt);
        gemm_mma<0,1,0><<<GG2, 256, GSMEM2, s>>>(feat, dwimg + (size_t)i * 32768, pw,
                                                 nullptr, nullptr, sum, sumq, nullptr);
        bn_finalize<<<1, 128, 0, s>>>(sum, sumq, lw_gamma + i * CH, lw_beta + i * CH, sc, sb);
        seg_sum_bn<<<EG, EB, 0, s>>>(pw, sc, sb, cl, seg);
        sub_segmean<<<EG, EB, 0, s>>>(pw, sc, sb, seg, cnt, cl);
        gemm_mma<0,2,0><<<GG2, 256, GSMEM2, s>>>(pw, dwimg + (size_t)(3 + i) * 32768, t,
                                                 nullptr, nullptr, nullptr, nullptr, gm);
        exp_seg<<<EG, EB, 0, s>>>(t, gm, cl, sgE);
        gemm_mma<0,1,0><<<GG2, 256, GSMEM2, s>>>(feat, dwimg + (size_t)(6 + i) * 32768, pf,
                                                 nullptr, nullptr, sum, sumq, nullptr);
        bn_finalize<<<1, 128, 0, s>>>(sum, sumq, proj_gamma + i * CH, proj_beta + i * CH, sc, sb);
        wmul_seg_bn<<<EG, EB, 0, s>>>(pf, sc, sb, t, gm, sgE, cl, sg2);
    };

    level_chain(0, 0);
    level_chain(1, st[0]);
    level_chain(2, st[1]);

    {
        cudaStream_t s = st[2];
        float* pf3 = pf4 + (size_t)3 * NC;
        float* sum  = sum8 + 3 * CH;
        float* sumq = sumq8 + 3 * CH;
        float* sc   = scale8 + 3 * CH;
        float* sb   = bias8 + 3 * CH;
        gemm_mma<0,1,0><<<GG2, 256, GSMEM2, s>>>(feat, dwimg + (size_t)9 * 32768, pf3,
                                                 nullptr, nullptr, sum, sumq, nullptr);
        bn_finalize<<<1, 128, 0, s>>>(sum, sumq, proj_gamma + 3 * CH, proj_beta + 3 * CH, sc, sb);
        gemm_mma<1,0,0><<<GG2, 256, GSMEM2, s>>>(pf3, dwimg + (size_t)10 * 32768, tf,
                                                 sc, sb, nullptr, nullptr, nullptr);
    }

    // ---- join ----
    for (int k = 0; k < 3; k++) cudaEventRecord(evJ[k], st[k]);
    for (int k = 0; k < 3; k++) cudaStreamWaitEvent(0, evJ[k], 0);

    // ---- epilogue ----
    float* sumF  = sum8 + 4 * CH;
    float* sumqF = sumq8 + 4 * CH;
    float* scF   = scale8 + 4 * CH;
    float* sbF   = bias8 + 4 * CH;

    agg_k<<<EG, EB>>>(adp, clusters, seg2, agg);
    gemm_mma<0,1,1><<<GG2, 256, GSMEM2>>>(agg, dwimg + (size_t)11 * 32768, tf,
                                          nullptr, nullptr, sumF, sumqF, nullptr);
    bn_finalize<<<1, 128>>>(sumF, sumqF, fuse_gamma, fuse_beta, scF, sbF);
    fusedres_hilo<<<EG, EB>>>(tf, scF, sbF, feat, fused, xhi, xlo);

    sconv_mma<<<SG2, 256, SSMEM>>>(xhi, xlo, nbr, wimg, ybuf, sumF, sumqF);
    bn_finalize<<<1, 128>>>(sumF, sumqF, bn1_gamma, bn1_beta, scF, sbF);
    bnact_hilo<<<EG, EB>>>(ybuf, scF, sbF, xhi, xlo);

    sconv_mma<<<SG2, 256, SSMEM>>>(xhi, xlo, nbr, wimg + (size_t)KT * 32768, dbuf, sumF, sumqF);
    bn_finalize<<<1, 128>>>(sumF, sumqF, bn2_gamma, bn2_beta, scF, sbF);
    final_k<<<EG, EB>>>(dbuf, scF, sbF, fused, out);
}

// round 14
// speedup vs baseline: 1.0296x; 1.0296x over previous
#include <cuda_runtime.h>
#include <cuda_bf16.h>
#include <math.h>

#define NV   65536
#define CH   128
#define NSEGS 1024
#define KT   27
#define NC   (NV*CH)
#define SEGS (NSEGS*CH)
#define SEGSTRIDE (3*SEGS)

typedef unsigned long long u64;
typedef unsigned int u32;

__device__ __forceinline__ float lrelu(float v) { return v >= 0.f ? v : 0.01f * v; }
__device__ __forceinline__ u32 enc_max(float f) {
    u32 u = __float_as_uint(f);
    return (u & 0x80000000u) ? ~u : (u | 0x80000000u);
}
__device__ __forceinline__ float dec_max(u32 k) {
    u32 u = (k & 0x80000000u) ? (k & 0x7FFFFFFFu) : ~k;
    return __uint_as_float(u);
}

// ---------------- scratch ----------------------------------------------------
__device__ float g_pw3[3*NC];
__device__ float g_t3[3*NC];
__device__ float g_pf4[4*NC];
__device__ float g_tf[NC];
__device__ float g_fused[NC];
__device__ float g_ybuf[NC];
__device__ float g_dbuf[NC];
__device__ float g_adp[NV*3];
__device__ float g_segall[3*SEGSTRIDE];   // per level: [seg | segE | seg2]
__device__ float g_cnt3[3*NSEGS];
__device__ float g_sum8[8*CH];
__device__ float g_sumq8[8*CH];
__device__ float g_scale8[8*CH];
__device__ float g_bias8[8*CH];
__device__ u32   g_gmax3[3];
__device__ __align__(256) __nv_bfloat16 g_wimg[2*KT*32768];
__device__ __align__(256) __nv_bfloat16 g_dwimg[12*32768];
__device__ __align__(256) __nv_bfloat16 g_xhi[NC];
__device__ __align__(256) __nv_bfloat16 g_xlo[NC];

// ======================= shared HMMA helpers ==================================
#define ROWB 272
#define T128 (128*ROWB)               // 34816
#define T64  (64*ROWB)                // 17408
// dense gemm (64x64): A_HI(T64) A_LO(T64) W_HI(T64) W_LO(T64)
#define G2_ALO  T64
#define G2_WHI  (2*T64)
#define G2_WLO  (3*T64)
#define GSMEM2  (4*T64)               // 69632 -> 3 CTAs/SM
// sconv (R12): Abuf0(HI,LO T128) Abuf1(HI,LO) W_HI W_LO
#define S_WHI   (4*T128)
#define S_WLO   (5*T128)
#define SSMEM   (6*T128)              // 208896 -> 1 CTA/SM

__device__ __forceinline__ u32 smem_u32(const void* p) {
    u32 a; asm("{ .reg .u64 t; cvta.to.shared.u64 t, %1; cvt.u32.u64 %0, t; }"
               : "=r"(a) : "l"(p));
    return a;
}
__device__ __forceinline__ void cp16(u32 dst, const void* src, u32 srcsz) {
    asm volatile("cp.async.cg.shared.global [%0], [%1], 16, %2;"
                 :: "r"(dst), "l"(src), "r"(srcsz) : "memory");
}
__device__ __forceinline__ void ldm4(u32 addr, u32& r0, u32& r1, u32& r2, u32& r3) {
    asm volatile("ldmatrix.sync.aligned.m8n8.x4.shared.b16 {%0,%1,%2,%3}, [%4];"
                 : "=r"(r0), "=r"(r1), "=r"(r2), "=r"(r3) : "r"(addr));
}
__device__ __forceinline__ void mma16816(float* c, const u32* a, const u32* b) {
    asm volatile(
        "mma.sync.aligned.m16n8k16.row.col.f32.bf16.bf16.f32 "
        "{%0,%1,%2,%3}, {%4,%5,%6,%7}, {%8,%9}, {%0,%1,%2,%3};"
        : "+f"(c[0]), "+f"(c[1]), "+f"(c[2]), "+f"(c[3])
        : "r"(a[0]), "r"(a[1]), "r"(a[2]), "r"(a[3]), "r"(b[0]), "r"(b[1]));
}

template<int NT>
__device__ __forceinline__ void mma_ld(u32 aHi, u32 aLo, u32 wHi, u32 wLo,
                                       float acc[2][NT][4], int mwarp, int nwarp, int lane)
{
    const int r = lane & 7, j = lane >> 3;
    const u32 aoff = (u32)(mwarp + (j & 1) * 8 + r) * ROWB + (u32)(j >> 1) * 16u;
    const u32 boff = (u32)(nwarp + (j >> 1) * 8 + r) * ROWB + (u32)(j & 1) * 16u;
#pragma unroll
    for (int kc = 0; kc < 8; kc++) {
        u32 ah[2][4], al[2][4];
#pragma unroll
        for (int mt = 0; mt < 2; mt++) {
            u32 adr = aoff + (u32)mt * (16u * ROWB) + (u32)kc * 32u;
            ldm4(aHi + adr, ah[mt][0], ah[mt][1], ah[mt][2], ah[mt][3]);
            ldm4(aLo + adr, al[mt][0], al[mt][1], al[mt][2], al[mt][3]);
        }
        u32 bh[NT][2], bl[NT][2];
#pragma unroll
        for (int np = 0; np < NT / 2; np++) {
            u32 bdr = boff + (u32)np * (16u * ROWB) + (u32)kc * 32u;
            ldm4(wHi + bdr, bh[2*np][0], bh[2*np][1], bh[2*np+1][0], bh[2*np+1][1]);
            ldm4(wLo + bdr, bl[2*np][0], bl[2*np][1], bl[2*np+1][0], bl[2*np+1][1]);
        }
#pragma unroll
        for (int mt = 0; mt < 2; mt++)
#pragma unroll
            for (int nt = 0; nt < NT; nt++) {
                mma16816(acc[mt][nt], ah[mt], bh[nt]);
                mma16816(acc[mt][nt], al[mt], bh[nt]);
                mma16816(acc[mt][nt], ah[mt], bl[nt]);
            }
    }
}

// ---------------- weight prep -------------------------------------------------
__global__ void wprep(const float* __restrict__ W1, const float* __restrict__ W2,
                      __nv_bfloat16* __restrict__ img)
{
    int b = blockIdx.x;
    const float* W = (b < KT ? W1 : W2) + (size_t)(b % KT) * CH * CH;
    __nv_bfloat16* o = img + (size_t)b * 32768;
    for (int u = threadIdx.x; u < 16384; u += blockDim.x) {
        int cout = u >> 7, cin = u & 127;
        float v = W[cin * CH + cout];
        __nv_bfloat16 h = __float2bfloat16(v);
        o[u]         = h;
        o[16384 + u] = __float2bfloat16(v - __bfloat162float(h));
    }
}

__global__ void dwprep(const float* __restrict__ lw, const float* __restrict__ ww,
                       const float* __restrict__ pj, const float* __restrict__ fw,
                       __nv_bfloat16* __restrict__ img)
{
    int b = blockIdx.x;
    const float* W;
    if (b < 3)       W = lw + (size_t)b * 16384;
    else if (b < 6)  W = ww + (size_t)(b - 3) * 16384;
    else if (b < 10) W = pj + (size_t)(b - 6) * 16384;
    else             W = fw + (size_t)(b - 10) * 16384;
    __nv_bfloat16* o = img + (size_t)b * 32768;
    for (int u = threadIdx.x; u < 16384; u += blockDim.x) {
        int n = u >> 7, k = u & 127;
        float v = W[k * CH + n];
        __nv_bfloat16 h = __float2bfloat16(v);
        o[u]         = h;
        o[16384 + u] = __float2bfloat16(v - __bfloat162float(h));
    }
}

// ======================= HMMA dense GEMM (64x64 tiles, 3 CTA/SM) ==============
// PRO: 0 plain; 1 lrelu(bn(A)); 2 A := sum_lvl adp*seg2 (agg on-the-fly)
// EPI: 1 colstats, 2 global-max. ACC: C += result.
template<int PRO, int EPI, int ACC>
__global__ __launch_bounds__(256, 3)
void gemm_mma(const float* __restrict__ A, const __nv_bfloat16* __restrict__ Wimg,
              float* __restrict__ Cc,
              const float* __restrict__ scp, const float* __restrict__ sbp,
              float* __restrict__ sumP, float* __restrict__ sumqP,
              u32* __restrict__ gmaxP,
              const int* __restrict__ clP, const float* __restrict__ adpP,
              const float* __restrict__ s2P)
{
    extern __shared__ char dsm[];
    const u32 sb = smem_u32(dsm);
    __shared__ float s_sc[128], s_sb[128];

    const int tid = threadIdx.x;
    const int wid = tid >> 5, lane = tid & 31;
    const int g = lane >> 2, tg = lane & 3;
    const int wm = wid & 1, wn = wid >> 1;
    const int brow = (blockIdx.x >> 1) * 64;
    const int bcol = (blockIdx.x & 1) * 64;

    {
        const int wr = tid >> 2, wq = tid & 3;
        u32 wdst = sb + G2_WHI + (u32)wr * ROWB + (u32)wq * 64;
        const char* whi = (const char*)(Wimg + (size_t)(bcol + wr) * 128) + wq * 64;
#pragma unroll
        for (int j = 0; j < 4; j++) {
            cp16(wdst + j * 16,       whi + j * 16, 16u);
            cp16(wdst + T64 + j * 16, whi + 32768 + j * 16, 16u);
        }
        asm volatile("cp.async.commit_group;" ::: "memory");
    }
    if (PRO == 1 && tid < 128) { s_sc[tid] = scp[tid]; s_sb[tid] = sbp[tid]; }

    const int ar = tid >> 2, aq = tid & 3;
    float4 av[8];
    if (PRO == 2) {
        int n = brow + ar;
        int c0 = clP[n], c1 = clP[NV + n], c2 = clP[2 * NV + n];
        float a0 = adpP[n * 3 + 0], a1 = adpP[n * 3 + 1], a2 = adpP[n * 3 + 2];
        const float4* r0 = (const float4*)(s2P + 0 * SEGSTRIDE + (size_t)c0 * CH + aq * 32);
        const float4* r1 = (const float4*)(s2P + 1 * SEGSTRIDE + (size_t)c1 * CH + aq * 32);
        const float4* r2 = (const float4*)(s2P + 2 * SEGSTRIDE + (size_t)c2 * CH + aq * 32);
#pragma unroll
        for (int j = 0; j < 8; j++) {
            float4 v0 = r0[j], v1 = r1[j], v2 = r2[j];
            av[j].x = a0 * v0.x + a1 * v1.x + a2 * v2.x;
            av[j].y = a0 * v0.y + a1 * v1.y + a2 * v2.y;
            av[j].z = a0 * v0.z + a1 * v1.z + a2 * v2.z;
            av[j].w = a0 * v0.w + a1 * v1.w + a2 * v2.w;
        }
    } else {
        const float4* Ap = (const float4*)(A + (size_t)(brow + ar) * CH + aq * 32);
#pragma unroll
        for (int j = 0; j < 8; j++) av[j] = Ap[j];
    }
    __syncthreads();

    {
        u64* hp = (u64*)(dsm + (u32)ar * ROWB + (u32)aq * 64);
        u64* lp = (u64*)(dsm + G2_ALO + (u32)ar * ROWB + (u32)aq * 64);
#pragma unroll
        for (int j = 0; j < 8; j++) {
            float4 v = av[j];
            if (PRO == 1) {
                int cb = aq * 32 + j * 4;
                v.x = lrelu(v.x * s_sc[cb]     + s_sb[cb]);
                v.y = lrelu(v.y * s_sc[cb + 1] + s_sb[cb + 1]);
                v.z = lrelu(v.z * s_sc[cb + 2] + s_sb[cb + 2]);
                v.w = lrelu(v.w * s_sc[cb + 3] + s_sb[cb + 3]);
            }
            __nv_bfloat162 h01 = __floats2bfloat162_rn(v.x, v.y);
            __nv_bfloat162 h23 = __floats2bfloat162_rn(v.z, v.w);
            float2 f01 = __bfloat1622float2(h01);
            float2 f23 = __bfloat1622float2(h23);
            __nv_bfloat162 l01 = __floats2bfloat162_rn(v.x - f01.x, v.y - f01.y);
            __nv_bfloat162 l23 = __floats2bfloat162_rn(v.z - f23.x, v.w - f23.y);
            hp[j] = ((u64)(*(u32*)&h23) << 32) | (u64)(*(u32*)&h01);
            lp[j] = ((u64)(*(u32*)&l23) << 32) | (u64)(*(u32*)&l01);
        }
    }
    asm volatile("cp.async.wait_group 0;" ::: "memory");
    __syncthreads();

    float acc[2][2][4];
#pragma unroll
    for (int mt = 0; mt < 2; mt++)
#pragma unroll
        for (int nt = 0; nt < 2; nt++)
#pragma unroll
            for (int q = 0; q < 4; q++) acc[mt][nt][q] = 0.f;

    mma_ld<2>(sb, sb + G2_ALO, sb + G2_WHI, sb + G2_WLO, acc, wm * 32, wn * 16, lane);

    float colS[2][2], colQ[2][2];
    if (EPI == 1) {
#pragma unroll
        for (int nt = 0; nt < 2; nt++) { colS[nt][0] = colS[nt][1] = 0.f;
                                         colQ[nt][0] = colQ[nt][1] = 0.f; }
    }
    float bmax = -3.4e38f;

#pragma unroll
    for (int mt = 0; mt < 2; mt++) {
        int row0 = brow + wm * 32 + mt * 16 + g;
#pragma unroll
        for (int nt = 0; nt < 2; nt++) {
            int col = bcol + wn * 16 + nt * 8 + tg * 2;
            float* p0 = Cc + (size_t)row0 * CH + col;
            float* p1 = Cc + (size_t)(row0 + 8) * CH + col;
            float c0 = acc[mt][nt][0], c1 = acc[mt][nt][1];
            float c2 = acc[mt][nt][2], c3 = acc[mt][nt][3];
            if (ACC) {
                float2 o0 = *(float2*)p0, o1 = *(float2*)p1;
                c0 += o0.x; c1 += o0.y; c2 += o1.x; c3 += o1.y;
            }
            if (EPI == 1) {
                colS[nt][0] += c0 + c2; colS[nt][1] += c1 + c3;
                colQ[nt][0] += c0 * c0 + c2 * c2; colQ[nt][1] += c1 * c1 + c3 * c3;
            }
            if (EPI == 2) bmax = fmaxf(bmax, fmaxf(fmaxf(c0, c1), fmaxf(c2, c3)));
            *(float2*)p0 = make_float2(c0, c1);
            *(float2*)p1 = make_float2(c2, c3);
        }
    }

    if (EPI == 1) {
        __syncthreads();
        float* red = (float*)dsm;
        if (tid < 128) red[tid] = 0.f;
        __syncthreads();
#pragma unroll
        for (int nt = 0; nt < 2; nt++) {
            int lc = wn * 16 + nt * 8 + tg * 2;
            atomicAdd(&red[lc],          colS[nt][0]);
            atomicAdd(&red[lc + 1],      colS[nt][1]);
            atomicAdd(&red[64 + lc],     colQ[nt][0]);
            atomicAdd(&red[64 + lc + 1], colQ[nt][1]);
        }
        __syncthreads();
        if (tid < 64) {
            atomicAdd(&sumP[bcol + tid],  red[tid]);
            atomicAdd(&sumqP[bcol + tid], red[64 + tid]);
        }
    }
    if (EPI == 2) {
#pragma unroll
        for (int o = 16; o; o >>= 1)
            bmax = fmaxf(bmax, __shfl_xor_sync(0xffffffffu, bmax, o));
        if (lane == 0) atomicMax(gmaxP, enc_max(bmax));
    }
}

// ======================= HMMA sparse conv (R12: 128x128, A double-buffered) ===
__global__ __launch_bounds__(256, 1)
void sconv_mma(const __nv_bfloat16* __restrict__ Xhi,
               const __nv_bfloat16* __restrict__ Xlo,
               const int* __restrict__ nbr,
               const __nv_bfloat16* __restrict__ Wimg,
               float* __restrict__ Out,
               float* __restrict__ sumP, float* __restrict__ sumqP)
{
    extern __shared__ char dsm[];
    const u32 sb = smem_u32(dsm);

    const int tid = threadIdx.x;
    const int wid = tid >> 5, lane = tid & 31;
    const int g = lane >> 2, tg = lane & 3;
    const int wm = wid & 3, wn = wid >> 2;
    const int brow = blockIdx.x * 128;
    const int cr = tid >> 1, chalf = tid & 1;
    const u32 rowB = (u32)cr * ROWB + (u32)chalf * 128;

    float acc[2][8][4];
#pragma unroll
    for (int mt = 0; mt < 2; mt++)
#pragma unroll
        for (int nt = 0; nt < 8; nt++)
#pragma unroll
            for (int q = 0; q < 4; q++) acc[mt][nt][q] = 0.f;

    {
        int n = nbr[(size_t)(brow + cr) * KT];
        bool valid = n < NV;
        u32 sz = valid ? 16u : 0u;
        const char* shi = (const char*)(Xhi + (size_t)(valid ? n : 0) * CH) + chalf * 128;
        const char* slo = (const char*)(Xlo + (size_t)(valid ? n : 0) * CH) + chalf * 128;
#pragma unroll
        for (int j = 0; j < 8; j++) {
            cp16(sb + rowB + j * 16,        shi + j * 16, sz);
            cp16(sb + T128 + rowB + j * 16, slo + j * 16, sz);
        }
        asm volatile("cp.async.commit_group;" ::: "memory");
    }

#pragma unroll 1
    for (int k = 0; k < KT; k++) {
        const u32 abase = sb + (u32)(k & 1) * (2 * T128);
        {
            const char* whi = (const char*)(Wimg + (size_t)k * 32768) + cr * 256 + chalf * 128;
#pragma unroll
            for (int j = 0; j < 8; j++) {
                cp16(sb + S_WHI + rowB + j * 16, whi + j * 16, 16u);
                cp16(sb + S_WLO + rowB + j * 16, whi + 32768 + j * 16, 16u);
            }
            asm volatile("cp.async.commit_group;" ::: "memory");
        }
        if (k < KT - 1) {
            const u32 pb = sb + (u32)((k + 1) & 1) * (2 * T128);
            int n = nbr[(size_t)(brow + cr) * KT + k + 1];
            bool valid = n < NV;
            u32 sz = valid ? 16u : 0u;
            const char* shi = (const char*)(Xhi + (size_t)(valid ? n : 0) * CH) + chalf * 128;
            const char* slo = (const char*)(Xlo + (size_t)(valid ? n : 0) * CH) + chalf * 128;
#pragma unroll
            for (int j = 0; j < 8; j++) {
                cp16(pb + rowB + j * 16,        shi + j * 16, sz);
                cp16(pb + T128 + rowB + j * 16, slo + j * 16, sz);
            }
            asm volatile("cp.async.commit_group;" ::: "memory");
            asm volatile("cp.async.wait_group 1;" ::: "memory");
        } else {
            asm volatile("cp.async.wait_group 0;" ::: "memory");
        }
        __syncthreads();

        mma_ld<8>(abase, abase + T128, sb + S_WHI, sb + S_WLO, acc,
                  wm * 32, wn * 64, lane);
        __syncthreads();
    }

    float colS[8][2], colQ[8][2];
#pragma unroll
    for (int nt = 0; nt < 8; nt++) { colS[nt][0] = colS[nt][1] = 0.f;
                                     colQ[nt][0] = colQ[nt][1] = 0.f; }
#pragma unroll
    for (int mt = 0; mt < 2; mt++) {
        int row0 = brow + wm * 32 + mt * 16 + g;
#pragma unroll
        for (int nt = 0; nt < 8; nt++) {
            int col = wn * 64 + nt * 8 + tg * 2;
            float c0 = acc[mt][nt][0], c1 = acc[mt][nt][1];
            float c2 = acc[mt][nt][2], c3 = acc[mt][nt][3];
            colS[nt][0] += c0 + c2; colS[nt][1] += c1 + c3;
            colQ[nt][0] += c0 * c0 + c2 * c2; colQ[nt][1] += c1 * c1 + c3 * c3;
            *(float2*)(Out + (size_t)row0 * CH + col)       = make_float2(c0, c1);
            *(float2*)(Out + (size_t)(row0 + 8) * CH + col) = make_float2(c2, c3);
        }
    }
    __syncthreads();
    float* red = (float*)dsm;
    if (tid < 256) red[tid] = 0.f;
    __syncthreads();
#pragma unroll
    for (int nt = 0; nt < 8; nt++) {
        int col = wn * 64 + nt * 8 + tg * 2;
        atomicAdd(&red[col],           colS[nt][0]);
        atomicAdd(&red[col + 1],       colS[nt][1]);
        atomicAdd(&red[128 + col],     colQ[nt][0]);
        atomicAdd(&red[128 + col + 1], colQ[nt][1]);
    }
    __syncthreads();
    if (tid < 128) {
        atomicAdd(&sumP[tid],  red[tid]);
        atomicAdd(&sumqP[tid], red[128 + tid]);
    }
}

// ---------------- BN finalize (self-zeroing) ----------------------------------
__global__ void bn_finalize(float* __restrict__ sum, float* __restrict__ sumsq,
                            const float* __restrict__ gamma, const float* __restrict__ beta,
                            float* __restrict__ scale, float* __restrict__ bias)
{
    int c = threadIdx.x;
    float s = sum[c], q = sumsq[c];
    sum[c] = 0.f; sumsq[c] = 0.f;
    float m = s * (1.f / (float)NV);
    float v = q * (1.f / (float)NV) - m * m;
    float sc = gamma[c] * rsqrtf(v + 1e-5f);
    scale[c] = sc;
    bias[c] = beta[c] - m * sc;
}

// ---------------- elementwise / segment kernels -------------------------------
__global__ void seg_count(const int* __restrict__ cl, float* __restrict__ cnt)
{
    int i = blockIdx.x * blockDim.x + threadIdx.x;
    atomicAdd(&cnt[cl[i]], 1.f);
}

// pw <- lrelu(bn(pw)); seg += pw
__global__ void seg_sum_bn(float* __restrict__ X, const float* __restrict__ sc,
                           const float* __restrict__ sb, const int* __restrict__ cl,
                           float* __restrict__ S)
{
    int i = blockIdx.x * blockDim.x + threadIdx.x;
    int n = i >> 7, c = i & 127;
    float v = lrelu(X[i] * sc[c] + sb[c]);
    X[i] = v;
    atomicAdd(&S[(size_t)cl[n] * CH + c], v);
}

__global__ void sub_segmean(float* __restrict__ X, const float* __restrict__ S,
                            const float* __restrict__ cnt, const int* __restrict__ cl)
{
    int i = blockIdx.x * blockDim.x + threadIdx.x;
    int n = i >> 7, c = i & 127;
    int s = cl[n];
    X[i] -= S[(size_t)s * CH + c] / fmaxf(cnt[s], 1.f);
}

__global__ void exp_seg(const float* __restrict__ T, const u32* __restrict__ gmaxP,
                        const int* __restrict__ cl, float* __restrict__ S)
{
    int i = blockIdx.x * blockDim.x + threadIdx.x;
    int n = i >> 7, c = i & 127;
    float e = expf(T[i] - dec_max(*gmaxP));
    atomicAdd(&S[(size_t)cl[n] * CH + c], e);
}

__global__ void wmul_seg_bn(const float* __restrict__ PF, const float* __restrict__ sc,
                            const float* __restrict__ sb, const float* __restrict__ T,
                            const u32* __restrict__ gmaxP, const float* __restrict__ S,
                            const int* __restrict__ cl, float* __restrict__ S2)
{
    int i = blockIdx.x * blockDim.x + threadIdx.x;
    int n = i >> 7, c = i & 127;
    int s = cl[n];
    float pfv = lrelu(PF[i] * sc[c] + sb[c]);
    float e = expf(T[i] - dec_max(*gmaxP));
    float v = pfv * (e / (S[(size_t)s * CH + c] + 1e-6f));
    atomicAdd(&S2[(size_t)s * CH + c], v);
}

__global__ void bnact_hilo(const float* __restrict__ X, const float* __restrict__ scale,
                           const float* __restrict__ bias,
                           __nv_bfloat16* __restrict__ Hi, __nv_bfloat16* __restrict__ Lo)
{
    int i = blockIdx.x * blockDim.x + threadIdx.x;
    int c = i & 127;
    float v = lrelu(X[i] * scale[c] + bias[c]);
    __nv_bfloat16 h = __float2bfloat16(v);
    Hi[i] = h;
    Lo[i] = __float2bfloat16(v - __bfloat162float(h));
}

__global__ void fusedres_hilo(const float* __restrict__ T, const float* __restrict__ sc,
                              const float* __restrict__ sb, const float* __restrict__ feat,
                              float* __restrict__ F,
                              __nv_bfloat16* __restrict__ Hi, __nv_bfloat16* __restrict__ Lo)
{
    int i = blockIdx.x * blockDim.x + threadIdx.x;
    int c = i & 127;
    float v = lrelu(T[i] * sc[c] + sb[c]) + feat[i];
    F[i] = v;
    __nv_bfloat16 h = __float2bfloat16(v);
    Hi[i] = h;
    Lo[i] = __float2bfloat16(v - __bfloat162float(h));
}

__global__ void final_k(const float* __restrict__ D, const float* __restrict__ sc,
                        const float* __restrict__ sb, const float* __restrict__ F,
                        float* __restrict__ O)
{
    int i = blockIdx.x * blockDim.x + threadIdx.x;
    int c = i & 127;
    O[i] = lrelu(D[i] * sc[c] + sb[c] + F[i]);
}

// ---------------- adaptive softmax -------------------------------------------
__global__ void adp_kernel(const float* __restrict__ feat, const float* __restrict__ aw,
                           float* __restrict__ adp)
{
    int row = blockIdx.x * 8 + (threadIdx.x >> 5);
    int lane = threadIdx.x & 31;
    float d0 = 0.f, d1 = 0.f, d2 = 0.f;
    const float* f = feat + (size_t)row * CH;
#pragma unroll
    for (int j = lane; j < CH; j += 32) {
        float v = f[j];
        d0 += v * aw[j * 3 + 0];
        d1 += v * aw[j * 3 + 1];
        d2 += v * aw[j * 3 + 2];
    }
#pragma unroll
    for (int o = 16; o; o >>= 1) {
        d0 += __shfl_xor_sync(0xffffffffu, d0, o);
        d1 += __shfl_xor_sync(0xffffffffu, d1, o);
        d2 += __shfl_xor_sync(0xffffffffu, d2, o);
    }
    if (lane == 0) {
        float m = fmaxf(d0, fmaxf(d1, d2));
        float e0 = expf(d0 - m), e1 = expf(d1 - m), e2 = expf(d2 - m);
        float inv = 1.f / (e0 + e1 + e2);
        adp[row * 3 + 0] = e0 * inv;
        adp[row * 3 + 1] = e1 * inv;
        adp[row * 3 + 2] = e2 * inv;
    }
}

// ---------------- orchestration ----------------------------------------------
extern "C" void kernel_launch(void* const* d_in, const int* in_sizes, int n_in,
                              void* d_out, int out_size)
{
    const float* feat       = (const float*)d_in[0];
    const int*   clusters   = (const int*)d_in[1];
    const int*   nbr        = (const int*)d_in[2];
    const float* lw_w       = (const float*)d_in[3];
    const float* lw_gamma   = (const float*)d_in[4];
    const float* lw_beta    = (const float*)d_in[5];
    const float* w_w        = (const float*)d_in[6];
    const float* proj_w     = (const float*)d_in[7];
    const float* proj_gamma = (const float*)d_in[8];
    const float* proj_beta  = (const float*)d_in[9];
    const float* adaptive_w = (const float*)d_in[10];
    const float* fuse_w     = (const float*)d_in[11];
    const float* fuse_gamma = (const float*)d_in[12];
    const float* fuse_beta  = (const float*)d_in[13];
    const float* conv1_w    = (const float*)d_in[14];
    const float* conv2_w    = (const float*)d_in[15];
    const float* bn1_gamma  = (const float*)d_in[16];
    const float* bn1_beta   = (const float*)d_in[17];
    const float* bn2_gamma  = (const float*)d_in[18];
    const float* bn2_beta   = (const float*)d_in[19];
    float* out = (float*)d_out;

    float *pw3, *t3, *pf4, *tf, *fused, *ybuf, *dbuf, *adp;
    float *segall, *cnt3, *sum8, *sumq8, *scale8, *bias8;
    u32 *gmax3;
    __nv_bfloat16 *wimg, *dwimg, *xhi, *xlo;
    cudaGetSymbolAddress((void**)&pw3, g_pw3);
    cudaGetSymbolAddress((void**)&t3, g_t3);
    cudaGetSymbolAddress((void**)&pf4, g_pf4);
    cudaGetSymbolAddress((void**)&tf, g_tf);
    cudaGetSymbolAddress((void**)&fused, g_fused);
    cudaGetSymbolAddress((void**)&ybuf, g_ybuf);
    cudaGetSymbolAddress((void**)&dbuf, g_dbuf);
    cudaGetSymbolAddress((void**)&adp, g_adp);
    cudaGetSymbolAddress((void**)&segall, g_segall);
    cudaGetSymbolAddress((void**)&cnt3, g_cnt3);
    cudaGetSymbolAddress((void**)&sum8, g_sum8);
    cudaGetSymbolAddress((void**)&sumq8, g_sumq8);
    cudaGetSymbolAddress((void**)&scale8, g_scale8);
    cudaGetSymbolAddress((void**)&bias8, g_bias8);
    cudaGetSymbolAddress((void**)&gmax3, g_gmax3);
    cudaGetSymbolAddress((void**)&wimg, g_wimg);
    cudaGetSymbolAddress((void**)&dwimg, g_dwimg);
    cudaGetSymbolAddress((void**)&xhi, g_xhi);
    cudaGetSymbolAddress((void**)&xlo, g_xlo);

    cudaFuncSetAttribute(sconv_mma, cudaFuncAttributeMaxDynamicSharedMemorySize, SSMEM);
    cudaFuncSetAttribute(gemm_mma<0,1,0>, cudaFuncAttributeMaxDynamicSharedMemorySize, GSMEM2);
    cudaFuncSetAttribute(gemm_mma<0,2,0>, cudaFuncAttributeMaxDynamicSharedMemorySize, GSMEM2);
    cudaFuncSetAttribute(gemm_mma<1,0,0>, cudaFuncAttributeMaxDynamicSharedMemorySize, GSMEM2);
    cudaFuncSetAttribute(gemm_mma<2,1,1>, cudaFuncAttributeMaxDynamicSharedMemorySize, GSMEM2);

    static cudaStream_t st[3];
    static cudaEvent_t evR, evJ[3];
    static int inited = 0;
    if (!inited) {
        for (int k = 0; k < 3; k++)
            cudaStreamCreateWithFlags(&st[k], cudaStreamNonBlocking);
        cudaEventCreateWithFlags(&evR, cudaEventDisableTiming);
        for (int k = 0; k < 3; k++)
            cudaEventCreateWithFlags(&evJ[k], cudaEventDisableTiming);
        inited = 1;
    }

    const int EB = 256;
    const int EG = NC / EB;
    const int GG2 = (NV / 64) * 2;

    // ---- prologue ----
    wprep<<<2 * KT, 256>>>(conv1_w, conv2_w, wimg);
    dwprep<<<12, 256>>>(lw_w, w_w, proj_w, fuse_w, dwimg);
    adp_kernel<<<NV / 8, 256>>>(feat, adaptive_w, adp);

    // ---- fork ----
    cudaEventRecord(evR, 0);
    for (int k = 0; k < 3; k++) cudaStreamWaitEvent(st[k], evR, 0);

    auto level_chain = [&](int i, cudaStream_t s) {
        const int* cl = clusters + (size_t)i * NV;
        float* pw = pw3 + (size_t)i * NC;
        float* t  = t3  + (size_t)i * NC;
        float* pf = pf4 + (size_t)i * NC;
        float* segbase = segall + (size_t)i * SEGSTRIDE;
        float* seg  = segbase;
        float* sgE  = segbase + SEGS;
        float* sg2  = segbase + 2 * SEGS;
        float* cnt  = cnt3 + (size_t)i * NSEGS;
        float* sum  = sum8 + i * CH;
        float* sumq = sumq8 + i * CH;
        float* sc   = scale8 + i * CH;
        float* sb   = bias8 + i * CH;
        u32* gm = gmax3 + i;

        cudaMemsetAsync(segbase, 0, (size_t)SEGSTRIDE * sizeof(float), s);
        cudaMemsetAsync(cnt, 0, NSEGS * sizeof(float), s);
        cudaMemsetAsync(gm, 0, sizeof(u32), s);
        seg_count<<<NV / 256, 256, 0, s>>>(cl, cnt);
        gemm_mma<0,1,0><<<GG2, 256, GSMEM2, s>>>(feat, dwimg + (size_t)i * 32768, pw,
                                                 nullptr, nullptr, sum, sumq, nullptr,
                                                 nullptr, nullptr, nullptr);
        bn_finalize<<<1, 128, 0, s>>>(sum, sumq, lw_gamma + i * CH, lw_beta + i * CH, sc, sb);
        seg_sum_bn<<<EG, EB, 0, s>>>(pw, sc, sb, cl, seg);
        sub_segmean<<<EG, EB, 0, s>>>(pw, seg, cnt, cl);
        gemm_mma<0,2,0><<<GG2, 256, GSMEM2, s>>>(pw, dwimg + (size_t)(3 + i) * 32768, t,
                                                 nullptr, nullptr, nullptr, nullptr, gm,
                                                 nullptr, nullptr, nullptr);
        exp_seg<<<EG, EB, 0, s>>>(t, gm, cl, sgE);
        gemm_mma<0,1,0><<<GG2, 256, GSMEM2, s>>>(feat, dwimg + (size_t)(6 + i) * 32768, pf,
                                                 nullptr, nullptr, sum, sumq, nullptr,
                                                 nullptr, nullptr, nullptr);
        bn_finalize<<<1, 128, 0, s>>>(sum, sumq, proj_gamma + i * CH, proj_beta + i * CH, sc, sb);
        wmul_seg_bn<<<EG, EB, 0, s>>>(pf, sc, sb, t, gm, sgE, cl, sg2);
    };

    level_chain(0, 0);
    level_chain(1, st[0]);
    level_chain(2, st[1]);

    {
        cudaStream_t s = st[2];
        float* pf3 = pf4 + (size_t)3 * NC;
        float* sum  = sum8 + 3 * CH;
        float* sumq = sumq8 + 3 * CH;
        float* sc   = scale8 + 3 * CH;
        float* sb   = bias8 + 3 * CH;
        gemm_mma<0,1,0><<<GG2, 256, GSMEM2, s>>>(feat, dwimg + (size_t)9 * 32768, pf3,
                                                 nullptr, nullptr, sum, sumq, nullptr,
                                                 nullptr, nullptr, nullptr);
        bn_finalize<<<1, 128, 0, s>>>(sum, sumq, proj_gamma + 3 * CH, proj_beta + 3 * CH, sc, sb);
        gemm_mma<1,0,0><<<GG2, 256, GSMEM2, s>>>(pf3, dwimg + (size_t)10 * 32768, tf,
                                                 sc, sb, nullptr, nullptr, nullptr,
                                                 nullptr, nullptr, nullptr);
    }

    // ---- join ----
    for (int k = 0; k < 3; k++) cudaEventRecord(evJ[k], st[k]);
    for (int k = 0; k < 3; k++) cudaStreamWaitEvent(0, evJ[k], 0);

    // ---- epilogue ----
    float* sumF  = sum8 + 4 * CH;
    float* sumqF = sumq8 + 4 * CH;
    float* scF   = scale8 + 4 * CH;
    float* sbF   = bias8 + 4 * CH;
    const float* seg2base = segall + 2 * SEGS;   // level l's seg2 at + l*SEGSTRIDE

    // fuse half 1: A = agg computed on the fly (PRO=2), accumulate into tf (+colstats)
    gemm_mma<2,1,1><<<GG2, 256, GSMEM2>>>(nullptr, dwimg + (size_t)11 * 32768, tf,
                                          nullptr, nullptr, sumF, sumqF, nullptr,
                                          clusters, adp, seg2base);
    bn_finalize<<<1, 128>>>(sumF, sumqF, fuse_gamma, fuse_beta, scF, sbF);
    fusedres_hilo<<<EG, EB>>>(tf, scF, sbF, feat, fused, xhi, xlo);

    sconv_mma<<<512, 256, SSMEM>>>(xhi, xlo, nbr, wimg, ybuf, sumF, sumqF);
    bn_finalize<<<1, 128>>>(sumF, sumqF, bn1_gamma, bn1_beta, scF, sbF);
    bnact_hilo<<<EG, EB>>>(ybuf, scF, sbF, xhi, xlo);

    sconv_mma<<<512, 256, SSMEM>>>(xhi, xlo, nbr, wimg + (size_t)KT * 32768, dbuf, sumF, sumqF);
    bn_finalize<<<1, 128>>>(sumF, sumqF, bn2_gamma, bn2_beta, scF, sbF);
    final_k<<<EG, EB>>>(dbuf, scF, sbF, fused, out);
}

// round 15
// speedup vs baseline: 1.0457x; 1.0156x over previous
#include <cuda_runtime.h>
#include <cuda_bf16.h>
#include <math.h>

#define NV   65536
#define CH   128
#define NSEGS 1024
#define KT   27
#define NC   (NV*CH)
#define SEGS (NSEGS*CH)
#define SEGSTRIDE (3*SEGS)

typedef unsigned long long u64;
typedef unsigned int u32;

__device__ __forceinline__ float lrelu(float v) { return v >= 0.f ? v : 0.01f * v; }
__device__ __forceinline__ u32 enc_max(float f) {
    u32 u = __float_as_uint(f);
    return (u & 0x80000000u) ? ~u : (u | 0x80000000u);
}
__device__ __forceinline__ float dec_max(u32 k) {
    u32 u = (k & 0x80000000u) ? (k & 0x7FFFFFFFu) : ~k;
    return __uint_as_float(u);
}

// ---------------- scratch ----------------------------------------------------
__device__ float g_pw3[3*NC];
__device__ float g_t3[3*NC];
__device__ float g_pf4[4*NC];
__device__ float g_tf[NC];
__device__ float g_agg[NC];
__device__ float g_fused[NC];
__device__ float g_ybuf[NC];
__device__ float g_dbuf[NC];
__device__ float g_adp[NV*3];
__device__ float g_segall[3*SEGSTRIDE];   // per level: [seg | segE | seg2]
__device__ float g_cnt3[3*NSEGS];
__device__ float g_sum8[8*CH];
__device__ float g_sumq8[8*CH];
__device__ float g_scale8[8*CH];
__device__ float g_bias8[8*CH];
__device__ u32   g_gmax3[3];
__device__ __align__(256) __nv_bfloat16 g_wimg[2*KT*32768];
__device__ __align__(256) __nv_bfloat16 g_dwimg[12*32768];
__device__ __align__(256) __nv_bfloat16 g_xhi[NC];
__device__ __align__(256) __nv_bfloat16 g_xlo[NC];

// ======================= shared HMMA helpers ==================================
#define ROWB 272
#define T128 (128*ROWB)               // 34816
#define T64  (64*ROWB)                // 17408
// dense gemm (64x64): A_HI(T64) A_LO(T64) W_HI(T64) W_LO(T64)
#define G2_ALO  T64
#define G2_WHI  (2*T64)
#define G2_WLO  (3*T64)
#define GSMEM2  (4*T64)               // 69632 -> 3 CTAs/SM
// sconv: A single (hi,lo) | W buf0 (hi,lo) | W buf1 (hi,lo)
#define S_WB0   (2*T128)
#define S_WB1   (4*T128)
#define SSMEM   (6*T128)              // 208896 -> 1 CTA/SM

__device__ __forceinline__ u32 smem_u32(const void* p) {
    u32 a; asm("{ .reg .u64 t; cvta.to.shared.u64 t, %1; cvt.u32.u64 %0, t; }"
               : "=r"(a) : "l"(p));
    return a;
}
__device__ __forceinline__ void cp16(u32 dst, const void* src, u32 srcsz) {
    asm volatile("cp.async.cg.shared.global [%0], [%1], 16, %2;"
                 :: "r"(dst), "l"(src), "r"(srcsz) : "memory");
}
__device__ __forceinline__ void ldm4(u32 addr, u32& r0, u32& r1, u32& r2, u32& r3) {
    asm volatile("ldmatrix.sync.aligned.m8n8.x4.shared.b16 {%0,%1,%2,%3}, [%4];"
                 : "=r"(r0), "=r"(r1), "=r"(r2), "=r"(r3) : "r"(addr));
}
__device__ __forceinline__ void mma16816(float* c, const u32* a, const u32* b) {
    asm volatile(
        "mma.sync.aligned.m16n8k16.row.col.f32.bf16.bf16.f32 "
        "{%0,%1,%2,%3}, {%4,%5,%6,%7}, {%8,%9}, {%0,%1,%2,%3};"
        : "+f"(c[0]), "+f"(c[1]), "+f"(c[2]), "+f"(c[3])
        : "r"(a[0]), "r"(a[1]), "r"(a[2]), "r"(a[3]), "r"(b[0]), "r"(b[1]));
}

template<int NT>
__device__ __forceinline__ void mma_ld(u32 aHi, u32 aLo, u32 wHi, u32 wLo,
                                       float acc[2][NT][4], int mwarp, int nwarp, int lane)
{
    const int r = lane & 7, j = lane >> 3;
    const u32 aoff = (u32)(mwarp + (j & 1) * 8 + r) * ROWB + (u32)(j >> 1) * 16u;
    const u32 boff = (u32)(nwarp + (j >> 1) * 8 + r) * ROWB + (u32)(j & 1) * 16u;
#pragma unroll
    for (int kc = 0; kc < 8; kc++) {
        u32 ah[2][4], al[2][4];
#pragma unroll
        for (int mt = 0; mt < 2; mt++) {
            u32 adr = aoff + (u32)mt * (16u * ROWB) + (u32)kc * 32u;
            ldm4(aHi + adr, ah[mt][0], ah[mt][1], ah[mt][2], ah[mt][3]);
            ldm4(aLo + adr, al[mt][0], al[mt][1], al[mt][2], al[mt][3]);
        }
        u32 bh[NT][2], bl[NT][2];
#pragma unroll
        for (int np = 0; np < NT / 2; np++) {
            u32 bdr = boff + (u32)np * (16u * ROWB) + (u32)kc * 32u;
            ldm4(wHi + bdr, bh[2*np][0], bh[2*np][1], bh[2*np+1][0], bh[2*np+1][1]);
            ldm4(wLo + bdr, bl[2*np][0], bl[2*np][1], bl[2*np+1][0], bl[2*np+1][1]);
        }
#pragma unroll
        for (int mt = 0; mt < 2; mt++)
#pragma unroll
            for (int nt = 0; nt < NT; nt++) {
                mma16816(acc[mt][nt], ah[mt], bh[nt]);
                mma16816(acc[mt][nt], al[mt], bh[nt]);
                mma16816(acc[mt][nt], ah[mt], bl[nt]);
            }
    }
}

// ---------------- weight prep -------------------------------------------------
__global__ void wprep(const float* __restrict__ W1, const float* __restrict__ W2,
                      __nv_bfloat16* __restrict__ img)
{
    int b = blockIdx.x;
    const float* W = (b < KT ? W1 : W2) + (size_t)(b % KT) * CH * CH;
    __nv_bfloat16* o = img + (size_t)b * 32768;
    for (int u = threadIdx.x; u < 16384; u += blockDim.x) {
        int cout = u >> 7, cin = u & 127;
        float v = W[cin * CH + cout];
        __nv_bfloat16 h = __float2bfloat16(v);
        o[u]         = h;
        o[16384 + u] = __float2bfloat16(v - __bfloat162float(h));
    }
}

__global__ void dwprep(const float* __restrict__ lw, const float* __restrict__ ww,
                       const float* __restrict__ pj, const float* __restrict__ fw,
                       __nv_bfloat16* __restrict__ img)
{
    int b = blockIdx.x;
    const float* W;
    if (b < 3)       W = lw + (size_t)b * 16384;
    else if (b < 6)  W = ww + (size_t)(b - 3) * 16384;
    else if (b < 10) W = pj + (size_t)(b - 6) * 16384;
    else             W = fw + (size_t)(b - 10) * 16384;
    __nv_bfloat16* o = img + (size_t)b * 32768;
    for (int u = threadIdx.x; u < 16384; u += blockDim.x) {
        int n = u >> 7, k = u & 127;
        float v = W[k * CH + n];
        __nv_bfloat16 h = __float2bfloat16(v);
        o[u]         = h;
        o[16384 + u] = __float2bfloat16(v - __bfloat162float(h));
    }
}

// ======================= HMMA dense GEMM (64x64 tiles, 3 CTA/SM) ==============
// PRO: 0 plain; 1 lrelu(bn(A)). EPI: 1 colstats, 2 global-max. ACC: C += result.
template<int PRO, int EPI, int ACC>
__global__ __launch_bounds__(256, 3)
void gemm_mma(const float* __restrict__ A, const __nv_bfloat16* __restrict__ Wimg,
              float* __restrict__ Cc,
              const float* __restrict__ scp, const float* __restrict__ sbp,
              float* __restrict__ sumP, float* __restrict__ sumqP,
              u32* __restrict__ gmaxP)
{
    extern __shared__ char dsm[];
    const u32 sb = smem_u32(dsm);
    __shared__ float s_sc[128], s_sb[128];

    const int tid = threadIdx.x;
    const int wid = tid >> 5, lane = tid & 31;
    const int g = lane >> 2, tg = lane & 3;
    const int wm = wid & 1, wn = wid >> 1;
    const int brow = (blockIdx.x >> 1) * 64;
    const int bcol = (blockIdx.x & 1) * 64;

    {
        const int wr = tid >> 2, wq = tid & 3;
        u32 wdst = sb + G2_WHI + (u32)wr * ROWB + (u32)wq * 64;
        const char* whi = (const char*)(Wimg + (size_t)(bcol + wr) * 128) + wq * 64;
#pragma unroll
        for (int j = 0; j < 4; j++) {
            cp16(wdst + j * 16,       whi + j * 16, 16u);
            cp16(wdst + T64 + j * 16, whi + 32768 + j * 16, 16u);
        }
        asm volatile("cp.async.commit_group;" ::: "memory");
    }
    if (PRO == 1 && tid < 128) { s_sc[tid] = scp[tid]; s_sb[tid] = sbp[tid]; }

    const int ar = tid >> 2, aq = tid & 3;
    float4 av[8];
    {
        const float4* Ap = (const float4*)(A + (size_t)(brow + ar) * CH + aq * 32);
#pragma unroll
        for (int j = 0; j < 8; j++) av[j] = Ap[j];
    }
    __syncthreads();

    {
        u64* hp = (u64*)(dsm + (u32)ar * ROWB + (u32)aq * 64);
        u64* lp = (u64*)(dsm + G2_ALO + (u32)ar * ROWB + (u32)aq * 64);
#pragma unroll
        for (int j = 0; j < 8; j++) {
            float4 v = av[j];
            if (PRO == 1) {
                int cb = aq * 32 + j * 4;
                v.x = lrelu(v.x * s_sc[cb]     + s_sb[cb]);
                v.y = lrelu(v.y * s_sc[cb + 1] + s_sb[cb + 1]);
                v.z = lrelu(v.z * s_sc[cb + 2] + s_sb[cb + 2]);
                v.w = lrelu(v.w * s_sc[cb + 3] + s_sb[cb + 3]);
            }
            __nv_bfloat162 h01 = __floats2bfloat162_rn(v.x, v.y);
            __nv_bfloat162 h23 = __floats2bfloat162_rn(v.z, v.w);
            float2 f01 = __bfloat1622float2(h01);
            float2 f23 = __bfloat1622float2(h23);
            __nv_bfloat162 l01 = __floats2bfloat162_rn(v.x - f01.x, v.y - f01.y);
            __nv_bfloat162 l23 = __floats2bfloat162_rn(v.z - f23.x, v.w - f23.y);
            hp[j] = ((u64)(*(u32*)&h23) << 32) | (u64)(*(u32*)&h01);
            lp[j] = ((u64)(*(u32*)&l23) << 32) | (u64)(*(u32*)&l01);
        }
    }
    asm volatile("cp.async.wait_group 0;" ::: "memory");
    __syncthreads();

    float acc[2][2][4];
#pragma unroll
    for (int mt = 0; mt < 2; mt++)
#pragma unroll
        for (int nt = 0; nt < 2; nt++)
#pragma unroll
            for (int q = 0; q < 4; q++) acc[mt][nt][q] = 0.f;

    mma_ld<2>(sb, sb + G2_ALO, sb + G2_WHI, sb + G2_WLO, acc, wm * 32, wn * 16, lane);

    float colS[2][2], colQ[2][2];
    if (EPI == 1) {
#pragma unroll
        for (int nt = 0; nt < 2; nt++) { colS[nt][0] = colS[nt][1] = 0.f;
                                         colQ[nt][0] = colQ[nt][1] = 0.f; }
    }
    float bmax = -3.4e38f;

#pragma unroll
    for (int mt = 0; mt < 2; mt++) {
        int row0 = brow + wm * 32 + mt * 16 + g;
#pragma unroll
        for (int nt = 0; nt < 2; nt++) {
            int col = bcol + wn * 16 + nt * 8 + tg * 2;
            float* p0 = Cc + (size_t)row0 * CH + col;
            float* p1 = Cc + (size_t)(row0 + 8) * CH + col;
            float c0 = acc[mt][nt][0], c1 = acc[mt][nt][1];
            float c2 = acc[mt][nt][2], c3 = acc[mt][nt][3];
            if (ACC) {
                float2 o0 = *(float2*)p0, o1 = *(float2*)p1;
                c0 += o0.x; c1 += o0.y; c2 += o1.x; c3 += o1.y;
            }
            if (EPI == 1) {
                colS[nt][0] += c0 + c2; colS[nt][1] += c1 + c3;
                colQ[nt][0] += c0 * c0 + c2 * c2; colQ[nt][1] += c1 * c1 + c3 * c3;
            }
            if (EPI == 2) bmax = fmaxf(bmax, fmaxf(fmaxf(c0, c1), fmaxf(c2, c3)));
            *(float2*)p0 = make_float2(c0, c1);
            *(float2*)p1 = make_float2(c2, c3);
        }
    }

    if (EPI == 1) {
        __syncthreads();
        float* red = (float*)dsm;
        if (tid < 128) red[tid] = 0.f;
        __syncthreads();
#pragma unroll
        for (int nt = 0; nt < 2; nt++) {
            int lc = wn * 16 + nt * 8 + tg * 2;
            atomicAdd(&red[lc],          colS[nt][0]);
            atomicAdd(&red[lc + 1],      colS[nt][1]);
            atomicAdd(&red[64 + lc],     colQ[nt][0]);
            atomicAdd(&red[64 + lc + 1], colQ[nt][1]);
        }
        __syncthreads();
        if (tid < 64) {
            atomicAdd(&sumP[bcol + tid],  red[tid]);
            atomicAdd(&sumqP[bcol + tid], red[64 + tid]);
        }
    }
    if (EPI == 2) {
#pragma unroll
        for (int o = 16; o; o >>= 1)
            bmax = fmaxf(bmax, __shfl_xor_sync(0xffffffffu, bmax, o));
        if (lane == 0) atomicMax(gmaxP, enc_max(bmax));
    }
}

// ====== HMMA sparse conv (128x128, A single-buffered, W double-buffered) ======
__global__ __launch_bounds__(256, 1)
void sconv_mma(const __nv_bfloat16* __restrict__ Xhi,
               const __nv_bfloat16* __restrict__ Xlo,
               const int* __restrict__ nbr,
               const __nv_bfloat16* __restrict__ Wimg,
               float* __restrict__ Out,
               float* __restrict__ sumP, float* __restrict__ sumqP)
{
    extern __shared__ char dsm[];
    const u32 sb = smem_u32(dsm);

    const int tid = threadIdx.x;
    const int wid = tid >> 5, lane = tid & 31;
    const int g = lane >> 2, tg = lane & 3;
    const int wm = wid & 3, wn = wid >> 2;
    const int brow = blockIdx.x * 128;
    const int cr = tid >> 1, chalf = tid & 1;
    const u32 rowB = (u32)cr * ROWB + (u32)chalf * 128;
    const size_t nbase = (size_t)(brow + cr) * KT;

    float acc[2][8][4];
#pragma unroll
    for (int mt = 0; mt < 2; mt++)
#pragma unroll
        for (int nt = 0; nt < 8; nt++)
#pragma unroll
            for (int q = 0; q < 4; q++) acc[mt][nt][q] = 0.f;

    auto issue_w = [&](int k, u32 wb) {
        const char* whi = (const char*)(Wimg + (size_t)k * 32768) + cr * 256 + chalf * 128;
#pragma unroll
        for (int j = 0; j < 8; j++) {
            cp16(wb + rowB + j * 16,        whi + j * 16, 16u);
            cp16(wb + T128 + rowB + j * 16, whi + 32768 + j * 16, 16u);
        }
        asm volatile("cp.async.commit_group;" ::: "memory");
    };
    auto issue_a = [&](int k) {
        int n = nbr[nbase + k];
        bool valid = n < NV;
        u32 sz = valid ? 16u : 0u;
        const char* shi = (const char*)(Xhi + (size_t)(valid ? n : 0) * CH) + chalf * 128;
        const char* slo = (const char*)(Xlo + (size_t)(valid ? n : 0) * CH) + chalf * 128;
#pragma unroll
        for (int j = 0; j < 8; j++) {
            cp16(sb + rowB + j * 16,        shi + j * 16, sz);
            cp16(sb + T128 + rowB + j * 16, slo + j * 16, sz);
        }
        asm volatile("cp.async.commit_group;" ::: "memory");
    };

    // prologue: W[0] prefetched
    issue_w(0, sb + S_WB0);

#pragma unroll 1
    for (int k = 0; k < KT; k++) {
        const u32 wb = sb + ((k & 1) ? S_WB1 : S_WB0);
        issue_a(k);                               // A[k] (exposed, 32KB L2-resident)
        if (k < KT - 1) {
            issue_w(k + 1, sb + ((k & 1) ? S_WB0 : S_WB1));   // W[k+1] prefetch
            asm volatile("cp.async.wait_group 1;" ::: "memory"); // W[k],A[k] done
        } else {
            asm volatile("cp.async.wait_group 0;" ::: "memory");
        }
        __syncthreads();

        mma_ld<8>(sb, sb + T128, wb, wb + T128, acc, wm * 32, wn * 64, lane);
        __syncthreads();   // A + wb free before next issue
    }

    float colS[8][2], colQ[8][2];
#pragma unroll
    for (int nt = 0; nt < 8; nt++) { colS[nt][0] = colS[nt][1] = 0.f;
                                     colQ[nt][0] = colQ[nt][1] = 0.f; }
#pragma unroll
    for (int mt = 0; mt < 2; mt++) {
        int row0 = brow + wm * 32 + mt * 16 + g;
#pragma unroll
        for (int nt = 0; nt < 8; nt++) {
            int col = wn * 64 + nt * 8 + tg * 2;
            float c0 = acc[mt][nt][0], c1 = acc[mt][nt][1];
            float c2 = acc[mt][nt][2], c3 = acc[mt][nt][3];
            colS[nt][0] += c0 + c2; colS[nt][1] += c1 + c3;
            colQ[nt][0] += c0 * c0 + c2 * c2; colQ[nt][1] += c1 * c1 + c3 * c3;
            *(float2*)(Out + (size_t)row0 * CH + col)       = make_float2(c0, c1);
            *(float2*)(Out + (size_t)(row0 + 8) * CH + col) = make_float2(c2, c3);
        }
    }
    __syncthreads();
    float* red = (float*)dsm;
    if (tid < 256) red[tid] = 0.f;
    __syncthreads();
#pragma unroll
    for (int nt = 0; nt < 8; nt++) {
        int col = wn * 64 + nt * 8 + tg * 2;
        atomicAdd(&red[col],           colS[nt][0]);
        atomicAdd(&red[col + 1],       colS[nt][1]);
        atomicAdd(&red[128 + col],     colQ[nt][0]);
        atomicAdd(&red[128 + col + 1], colQ[nt][1]);
    }
    __syncthreads();
    if (tid < 128) {
        atomicAdd(&sumP[tid],  red[tid]);
        atomicAdd(&sumqP[tid], red[128 + tid]);
    }
}

// ---------------- BN finalize (self-zeroing) ----------------------------------
__global__ void bn_finalize(float* __restrict__ sum, float* __restrict__ sumsq,
                            const float* __restrict__ gamma, const float* __restrict__ beta,
                            float* __restrict__ scale, float* __restrict__ bias)
{
    int c = threadIdx.x;
    float s = sum[c], q = sumsq[c];
    sum[c] = 0.f; sumsq[c] = 0.f;
    float m = s * (1.f / (float)NV);
    float v = q * (1.f / (float)NV) - m * m;
    float sc = gamma[c] * rsqrtf(v + 1e-5f);
    scale[c] = sc;
    bias[c] = beta[c] - m * sc;
}

// ---------------- elementwise / segment kernels -------------------------------
__global__ void seg_count(const int* __restrict__ cl, float* __restrict__ cnt)
{
    int i = blockIdx.x * blockDim.x + threadIdx.x;
    atomicAdd(&cnt[cl[i]], 1.f);
}

__global__ void seg_sum_bn(float* __restrict__ X, const float* __restrict__ sc,
                           const float* __restrict__ sb, const int* __restrict__ cl,
                           float* __restrict__ S)
{
    int i = blockIdx.x * blockDim.x + threadIdx.x;
    int n = i >> 7, c = i & 127;
    float v = lrelu(X[i] * sc[c] + sb[c]);
    X[i] = v;
    atomicAdd(&S[(size_t)cl[n] * CH + c], v);
}

__global__ void sub_segmean(float* __restrict__ X, const float* __restrict__ S,
                            const float* __restrict__ cnt, const int* __restrict__ cl)
{
    int i = blockIdx.x * blockDim.x + threadIdx.x;
    int n = i >> 7, c = i & 127;
    int s = cl[n];
    X[i] -= S[(size_t)s * CH + c] / fmaxf(cnt[s], 1.f);
}

__global__ void exp_seg(const float* __restrict__ T, const u32* __restrict__ gmaxP,
                        const int* __restrict__ cl, float* __restrict__ S)
{
    int i = blockIdx.x * blockDim.x + threadIdx.x;
    int n = i >> 7, c = i & 127;
    float e = expf(T[i] - dec_max(*gmaxP));
    atomicAdd(&S[(size_t)cl[n] * CH + c], e);
}

__global__ void wmul_seg_bn(const float* __restrict__ PF, const float* __restrict__ sc,
                            const float* __restrict__ sb, const float* __restrict__ T,
                            const u32* __restrict__ gmaxP, const float* __restrict__ S,
                            const int* __restrict__ cl, float* __restrict__ S2)
{
    int i = blockIdx.x * blockDim.x + threadIdx.x;
    int n = i >> 7, c = i & 127;
    int s = cl[n];
    float pfv = lrelu(PF[i] * sc[c] + sb[c]);
    float e = expf(T[i] - dec_max(*gmaxP));
    float v = pfv * (e / (S[(size_t)s * CH + c] + 1e-6f));
    atomicAdd(&S2[(size_t)s * CH + c], v);
}

// agg[n,c] = sum_lvl adp[n,lvl] * seg2[lvl][cl[lvl][n], c]  (seg2 stride = SEGSTRIDE)
__global__ void agg_k(const float* __restrict__ adp, const int* __restrict__ clusters,
                      const float* __restrict__ S2, float* __restrict__ AGG)
{
    int i = blockIdx.x * blockDim.x + threadIdx.x;
    int n = i >> 7, c = i & 127;
    float r = 0.f;
#pragma unroll
    for (int lvl = 0; lvl < 3; lvl++) {
        int s = clusters[(size_t)lvl * NV + n];
        r += adp[n * 3 + lvl] * S2[(size_t)lvl * SEGSTRIDE + (size_t)s * CH + c];
    }
    AGG[i] = r;
}

__global__ void bnact_hilo(const float* __restrict__ X, const float* __restrict__ scale,
                           const float* __restrict__ bias,
                           __nv_bfloat16* __restrict__ Hi, __nv_bfloat16* __restrict__ Lo)
{
    int i = blockIdx.x * blockDim.x + threadIdx.x;
    int c = i & 127;
    float v = lrelu(X[i] * scale[c] + bias[c]);
    __nv_bfloat16 h = __float2bfloat16(v);
    Hi[i] = h;
    Lo[i] = __float2bfloat16(v - __bfloat162float(h));
}

__global__ void fusedres_hilo(const float* __restrict__ T, const float* __restrict__ sc,
                              const float* __restrict__ sb, const float* __restrict__ feat,
                              float* __restrict__ F,
                              __nv_bfloat16* __restrict__ Hi, __nv_bfloat16* __restrict__ Lo)
{
    int i = blockIdx.x * blockDim.x + threadIdx.x;
    int c = i & 127;
    float v = lrelu(T[i] * sc[c] + sb[c]) + feat[i];
    F[i] = v;
    __nv_bfloat16 h = __float2bfloat16(v);
    Hi[i] = h;
    Lo[i] = __float2bfloat16(v - __bfloat162float(h));
}

__global__ void final_k(const float* __restrict__ D, const float* __restrict__ sc,
                        const float* __restrict__ sb, const float* __restrict__ F,
                        float* __restrict__ O)
{
    int i = blockIdx.x * blockDim.x + threadIdx.x;
    int c = i & 127;
    O[i] = lrelu(D[i] * sc[c] + sb[c] + F[i]);
}

// ---------------- adaptive softmax -------------------------------------------
__global__ void adp_kernel(const float* __restrict__ feat, const float* __restrict__ aw,
                           float* __restrict__ adp)
{
    int row = blockIdx.x * 8 + (threadIdx.x >> 5);
    int lane = threadIdx.x & 31;
    float d0 = 0.f, d1 = 0.f, d2 = 0.f;
    const float* f = feat + (size_t)row * CH;
#pragma unroll
    for (int j = lane; j < CH; j += 32) {
        float v = f[j];
        d0 += v * aw[j * 3 + 0];
        d1 += v * aw[j * 3 + 1];
        d2 += v * aw[j * 3 + 2];
    }
#pragma unroll
    for (int o = 16; o; o >>= 1) {
        d0 += __shfl_xor_sync(0xffffffffu, d0, o);
        d1 += __shfl_xor_sync(0xffffffffu, d1, o);
        d2 += __shfl_xor_sync(0xffffffffu, d2, o);
    }
    if (lane == 0) {
        float m = fmaxf(d0, fmaxf(d1, d2));
        float e0 = expf(d0 - m), e1 = expf(d1 - m), e2 = expf(d2 - m);
        float inv = 1.f / (e0 + e1 + e2);
        adp[row * 3 + 0] = e0 * inv;
        adp[row * 3 + 1] = e1 * inv;
        adp[row * 3 + 2] = e2 * inv;
    }
}

// ---------------- orchestration ----------------------------------------------
extern "C" void kernel_launch(void* const* d_in, const int* in_sizes, int n_in,
                              void* d_out, int out_size)
{
    const float* feat       = (const float*)d_in[0];
    const int*   clusters   = (const int*)d_in[1];
    const int*   nbr        = (const int*)d_in[2];
    const float* lw_w       = (const float*)d_in[3];
    const float* lw_gamma   = (const float*)d_in[4];
    const float* lw_beta    = (const float*)d_in[5];
    const float* w_w        = (const float*)d_in[6];
    const float* proj_w     = (const float*)d_in[7];
    const float* proj_gamma = (const float*)d_in[8];
    const float* proj_beta  = (const float*)d_in[9];
    const float* adaptive_w = (const float*)d_in[10];
    const float* fuse_w     = (const float*)d_in[11];
    const float* fuse_gamma = (const float*)d_in[12];
    const float* fuse_beta  = (const float*)d_in[13];
    const float* conv1_w    = (const float*)d_in[14];
    const float* conv2_w    = (const float*)d_in[15];
    const float* bn1_gamma  = (const float*)d_in[16];
    const float* bn1_beta   = (const float*)d_in[17];
    const float* bn2_gamma  = (const float*)d_in[18];
    const float* bn2_beta   = (const float*)d_in[19];
    float* out = (float*)d_out;

    float *pw3, *t3, *pf4, *tf, *agg, *fused, *ybuf, *dbuf, *adp;
    float *segall, *cnt3, *sum8, *sumq8, *scale8, *bias8;
    u32 *gmax3;
    __nv_bfloat16 *wimg, *dwimg, *xhi, *xlo;
    cudaGetSymbolAddress((void**)&pw3, g_pw3);
    cudaGetSymbolAddress((void**)&t3, g_t3);
    cudaGetSymbolAddress((void**)&pf4, g_pf4);
    cudaGetSymbolAddress((void**)&tf, g_tf);
    cudaGetSymbolAddress((void**)&agg, g_agg);
    cudaGetSymbolAddress((void**)&fused, g_fused);
    cudaGetSymbolAddress((void**)&ybuf, g_ybuf);
    cudaGetSymbolAddress((void**)&dbuf, g_dbuf);
    cudaGetSymbolAddress((void**)&adp, g_adp);
    cudaGetSymbolAddress((void**)&segall, g_segall);
    cudaGetSymbolAddress((void**)&cnt3, g_cnt3);
    cudaGetSymbolAddress((void**)&sum8, g_sum8);
    cudaGetSymbolAddress((void**)&sumq8, g_sumq8);
    cudaGetSymbolAddress((void**)&scale8, g_scale8);
    cudaGetSymbolAddress((void**)&bias8, g_bias8);
    cudaGetSymbolAddress((void**)&gmax3, g_gmax3);
    cudaGetSymbolAddress((void**)&wimg, g_wimg);
    cudaGetSymbolAddress((void**)&dwimg, g_dwimg);
    cudaGetSymbolAddress((void**)&xhi, g_xhi);
    cudaGetSymbolAddress((void**)&xlo, g_xlo);

    cudaFuncSetAttribute(sconv_mma, cudaFuncAttributeMaxDynamicSharedMemorySize, SSMEM);
    cudaFuncSetAttribute(gemm_mma<0,1,0>, cudaFuncAttributeMaxDynamicSharedMemorySize, GSMEM2);
    cudaFuncSetAttribute(gemm_mma<0,2,0>, cudaFuncAttributeMaxDynamicSharedMemorySize, GSMEM2);
    cudaFuncSetAttribute(gemm_mma<1,0,0>, cudaFuncAttributeMaxDynamicSharedMemorySize, GSMEM2);
    cudaFuncSetAttribute(gemm_mma<0,1,1>, cudaFuncAttributeMaxDynamicSharedMemorySize, GSMEM2);

    static cudaStream_t st[3];
    static cudaEvent_t evR, evJ[3];
    static int inited = 0;
    if (!inited) {
        for (int k = 0; k < 3; k++)
            cudaStreamCreateWithFlags(&st[k], cudaStreamNonBlocking);
        cudaEventCreateWithFlags(&evR, cudaEventDisableTiming);
        for (int k = 0; k < 3; k++)
            cudaEventCreateWithFlags(&evJ[k], cudaEventDisableTiming);
        inited = 1;
    }

    const int EB = 256;
    const int EG = NC / EB;
    const int GG2 = (NV / 64) * 2;

    // ---- prologue ----
    wprep<<<2 * KT, 256>>>(conv1_w, conv2_w, wimg);
    dwprep<<<12, 256>>>(lw_w, w_w, proj_w, fuse_w, dwimg);
    adp_kernel<<<NV / 8, 256>>>(feat, adaptive_w, adp);

    // ---- fork ----
    cudaEventRecord(evR, 0);
    for (int k = 0; k < 3; k++) cudaStreamWaitEvent(st[k], evR, 0);

    auto level_chain = [&](int i, cudaStream_t s) {
        const int* cl = clusters + (size_t)i * NV;
        float* pw = pw3 + (size_t)i * NC;
        float* t  = t3  + (size_t)i * NC;
        float* pf = pf4 + (size_t)i * NC;
        float* segbase = segall + (size_t)i * SEGSTRIDE;
        float* seg  = segbase;
        float* sgE  = segbase + SEGS;
        float* sg2  = segbase + 2 * SEGS;
        float* cnt  = cnt3 + (size_t)i * NSEGS;
        float* sum  = sum8 + i * CH;
        float* sumq = sumq8 + i * CH;
        float* sc   = scale8 + i * CH;
        float* sb   = bias8 + i * CH;
        u32* gm = gmax3 + i;

        cudaMemsetAsync(segbase, 0, (size_t)SEGSTRIDE * sizeof(float), s);
        cudaMemsetAsync(cnt, 0, NSEGS * sizeof(float), s);
        cudaMemsetAsync(gm, 0, sizeof(u32), s);
        seg_count<<<NV / 256, 256, 0, s>>>(cl, cnt);
        gemm_mma<0,1,0><<<GG2, 256, GSMEM2, s>>>(feat, dwimg + (size_t)i * 32768, pw,
                                                 nullptr, nullptr, sum, sumq, nullptr);
        bn_finalize<<<1, 128, 0, s>>>(sum, sumq, lw_gamma + i * CH, lw_beta + i * CH, sc, sb);
        seg_sum_bn<<<EG, EB, 0, s>>>(pw, sc, sb, cl, seg);
        sub_segmean<<<EG, EB, 0, s>>>(pw, seg, cnt, cl);
        gemm_mma<0,2,0><<<GG2, 256, GSMEM2, s>>>(pw, dwimg + (size_t)(3 + i) * 32768, t,
                                                 nullptr, nullptr, nullptr, nullptr, gm);
        exp_seg<<<EG, EB, 0, s>>>(t, gm, cl, sgE);
        gemm_mma<0,1,0><<<GG2, 256, GSMEM2, s>>>(feat, dwimg + (size_t)(6 + i) * 32768, pf,
                                                 nullptr, nullptr, sum, sumq, nullptr);
        bn_finalize<<<1, 128, 0, s>>>(sum, sumq, proj_gamma + i * CH, proj_beta + i * CH, sc, sb);
        wmul_seg_bn<<<EG, EB, 0, s>>>(pf, sc, sb, t, gm, sgE, cl, sg2);
    };

    level_chain(0, 0);
    level_chain(1, st[0]);
    level_chain(2, st[1]);

    {
        cudaStream_t s = st[2];
        float* pf3 = pf4 + (size_t)3 * NC;
        float* sum  = sum8 + 3 * CH;
        float* sumq = sumq8 + 3 * CH;
        float* sc   = scale8 + 3 * CH;
        float* sb   = bias8 + 3 * CH;
        gemm_mma<0,1,0><<<GG2, 256, GSMEM2, s>>>(feat, dwimg + (size_t)9 * 32768, pf3,
                                                 nullptr, nullptr, sum, sumq, nullptr);
        bn_finalize<<<1, 128, 0, s>>>(sum, sumq, proj_gamma + 3 * CH, proj_beta + 3 * CH, sc, sb);
        gemm_mma<1,0,0><<<GG2, 256, GSMEM2, s>>>(pf3, dwimg + (size_t)10 * 32768, tf,
                                                 sc, sb, nullptr, nullptr, nullptr);
    }

    // ---- join ----
    for (int k = 0; k < 3; k++) cudaEventRecord(evJ[k], st[k]);
    for (int k = 0; k < 3; k++) cudaStreamWaitEvent(0, evJ[k], 0);

    // ---- epilogue ----
    float* sumF  = sum8 + 4 * CH;
    float* sumqF = sumq8 + 4 * CH;
    float* scF   = scale8 + 4 * CH;
    float* sbF   = bias8 + 4 * CH;

    agg_k<<<EG, EB>>>(adp, clusters, segall + 2 * SEGS, agg);
    gemm_mma<0,1,1><<<GG2, 256, GSMEM2>>>(agg, dwimg + (size_t)11 * 32768, tf,
                                          nullptr, nullptr, sumF, sumqF, nullptr);
    bn_finalize<<<1, 128>>>(sumF, sumqF, fuse_gamma, fuse_beta, scF, sbF);
    fusedres_hilo<<<EG, EB>>>(tf, scF, sbF, feat, fused, xhi, xlo);

    sconv_mma<<<512, 256, SSMEM>>>(xhi, xlo, nbr, wimg, ybuf, sumF, sumqF);
    bn_finalize<<<1, 128>>>(sumF, sumqF, bn1_gamma, bn1_beta, scF, sbF);
    bnact_hilo<<<EG, EB>>>(ybuf, scF, sbF, xhi, xlo);

    sconv_mma<<<512, 256, SSMEM>>>(xhi, xlo, nbr, wimg + (size_t)KT * 32768, dbuf, sumF, sumqF);
    bn_finalize<<<1, 128>>>(sumF, sumqF, bn2_gamma, bn2_beta, scF, sbF);
    final_k<<<EG, EB>>>(dbuf, scF, sbF, fused, out);
}

// round 16
// speedup vs baseline: 1.0512x; 1.0052x over previous
#include <cuda_runtime.h>
#include <cuda_bf16.h>
#include <math.h>

#define NV   65536
#define CH   128
#define NSEGS 1024
#define KT   27
#define NC   (NV*CH)
#define SEGS (NSEGS*CH)
#define SEGSTRIDE (3*SEGS)

typedef unsigned long long u64;
typedef unsigned int u32;

__device__ __forceinline__ float lrelu(float v) { return v >= 0.f ? v : 0.01f * v; }

// ---------------- scratch ----------------------------------------------------
__device__ float g_pw3[3*NC];
__device__ float g_t3[3*NC];
__device__ float g_pf4[4*NC];
__device__ float g_tf[NC];
__device__ float g_agg[NC];
__device__ float g_fused[NC];
__device__ float g_ybuf[NC];
__device__ float g_dbuf[NC];
__device__ float g_adp[NV*3];
__device__ float g_segall[3*SEGSTRIDE];   // per level: [seg | segE | seg2]
__device__ float g_cnt3[3*NSEGS];
__device__ float g_sum8[8*CH];
__device__ float g_sumq8[8*CH];
__device__ float g_scale8[8*CH];
__device__ float g_bias8[8*CH];
__device__ __align__(256) __nv_bfloat16 g_wimg[2*KT*32768];
__device__ __align__(256) __nv_bfloat16 g_dwimg[12*32768];
__device__ __align__(256) __nv_bfloat16 g_xhi[NC];
__device__ __align__(256) __nv_bfloat16 g_xlo[NC];

// ======================= shared HMMA helpers ==================================
#define ROWB 272
#define T128 (128*ROWB)               // 34816
#define T64  (64*ROWB)                // 17408
#define G2_ALO  T64
#define G2_WHI  (2*T64)
#define G2_WLO  (3*T64)
#define GSMEM2  (4*T64)               // 69632 -> 3 CTAs/SM
#define S_WB0   (2*T128)
#define S_WB1   (4*T128)
#define SSMEM   (6*T128)              // 208896 -> 1 CTA/SM

__device__ __forceinline__ u32 smem_u32(const void* p) {
    u32 a; asm("{ .reg .u64 t; cvta.to.shared.u64 t, %1; cvt.u32.u64 %0, t; }"
               : "=r"(a) : "l"(p));
    return a;
}
__device__ __forceinline__ void cp16(u32 dst, const void* src, u32 srcsz) {
    asm volatile("cp.async.cg.shared.global [%0], [%1], 16, %2;"
                 :: "r"(dst), "l"(src), "r"(srcsz) : "memory");
}
__device__ __forceinline__ void ldm4(u32 addr, u32& r0, u32& r1, u32& r2, u32& r3) {
    asm volatile("ldmatrix.sync.aligned.m8n8.x4.shared.b16 {%0,%1,%2,%3}, [%4];"
                 : "=r"(r0), "=r"(r1), "=r"(r2), "=r"(r3) : "r"(addr));
}
__device__ __forceinline__ void mma16816(float* c, const u32* a, const u32* b) {
    asm volatile(
        "mma.sync.aligned.m16n8k16.row.col.f32.bf16.bf16.f32 "
        "{%0,%1,%2,%3}, {%4,%5,%6,%7}, {%8,%9}, {%0,%1,%2,%3};"
        : "+f"(c[0]), "+f"(c[1]), "+f"(c[2]), "+f"(c[3])
        : "r"(a[0]), "r"(a[1]), "r"(a[2]), "r"(a[3]), "r"(b[0]), "r"(b[1]));
}

template<int NT>
__device__ __forceinline__ void mma_ld(u32 aHi, u32 aLo, u32 wHi, u32 wLo,
                                       float acc[2][NT][4], int mwarp, int nwarp, int lane)
{
    const int r = lane & 7, j = lane >> 3;
    const u32 aoff = (u32)(mwarp + (j & 1) * 8 + r) * ROWB + (u32)(j >> 1) * 16u;
    const u32 boff = (u32)(nwarp + (j >> 1) * 8 + r) * ROWB + (u32)(j & 1) * 16u;
#pragma unroll
    for (int kc = 0; kc < 8; kc++) {
        u32 ah[2][4], al[2][4];
#pragma unroll
        for (int mt = 0; mt < 2; mt++) {
            u32 adr = aoff + (u32)mt * (16u * ROWB) + (u32)kc * 32u;
            ldm4(aHi + adr, ah[mt][0], ah[mt][1], ah[mt][2], ah[mt][3]);
            ldm4(aLo + adr, al[mt][0], al[mt][1], al[mt][2], al[mt][3]);
        }
        u32 bh[NT][2], bl[NT][2];
#pragma unroll
        for (int np = 0; np < NT / 2; np++) {
            u32 bdr = boff + (u32)np * (16u * ROWB) + (u32)kc * 32u;
            ldm4(wHi + bdr, bh[2*np][0], bh[2*np][1], bh[2*np+1][0], bh[2*np+1][1]);
            ldm4(wLo + bdr, bl[2*np][0], bl[2*np][1], bl[2*np+1][0], bl[2*np+1][1]);
        }
#pragma unroll
        for (int mt = 0; mt < 2; mt++)
#pragma unroll
            for (int nt = 0; nt < NT; nt++) {
                mma16816(acc[mt][nt], ah[mt], bh[nt]);
                mma16816(acc[mt][nt], al[mt], bh[nt]);
                mma16816(acc[mt][nt], ah[mt], bl[nt]);
            }
    }
}

// ---------------- weight prep -------------------------------------------------
__global__ void wprep(const float* __restrict__ W1, const float* __restrict__ W2,
                      __nv_bfloat16* __restrict__ img)
{
    int b = blockIdx.x;
    const float* W = (b < KT ? W1 : W2) + (size_t)(b % KT) * CH * CH;
    __nv_bfloat16* o = img + (size_t)b * 32768;
    for (int u = threadIdx.x; u < 16384; u += blockDim.x) {
        int cout = u >> 7, cin = u & 127;
        float v = W[cin * CH + cout];
        __nv_bfloat16 h = __float2bfloat16(v);
        o[u]         = h;
        o[16384 + u] = __float2bfloat16(v - __bfloat162float(h));
    }
}

__global__ void dwprep(const float* __restrict__ lw, const float* __restrict__ ww,
                       const float* __restrict__ pj, const float* __restrict__ fw,
                       __nv_bfloat16* __restrict__ img)
{
    int b = blockIdx.x;
    const float* W;
    if (b < 3)       W = lw + (size_t)b * 16384;
    else if (b < 6)  W = ww + (size_t)(b - 3) * 16384;
    else if (b < 10) W = pj + (size_t)(b - 6) * 16384;
    else             W = fw + (size_t)(b - 10) * 16384;
    __nv_bfloat16* o = img + (size_t)b * 32768;
    for (int u = threadIdx.x; u < 16384; u += blockDim.x) {
        int n = u >> 7, k = u & 127;
        float v = W[k * CH + n];
        __nv_bfloat16 h = __float2bfloat16(v);
        o[u]         = h;
        o[16384 + u] = __float2bfloat16(v - __bfloat162float(h));
    }
}

// ======================= HMMA dense GEMM (64x64 tiles, 3 CTA/SM) ==============
// PRO: 0 plain; 1 lrelu(bn(A)).
// EPI: 0 none; 1 colstats; 3 exp + segment-sum (writes exp to C, segE atomics)
// ACC: C += result.
template<int PRO, int EPI, int ACC>
__global__ __launch_bounds__(256, 3)
void gemm_mma(const float* __restrict__ A, const __nv_bfloat16* __restrict__ Wimg,
              float* __restrict__ Cc,
              const float* __restrict__ scp, const float* __restrict__ sbp,
              float* __restrict__ sumP, float* __restrict__ sumqP,
              const int* __restrict__ clP, float* __restrict__ segEP)
{
    extern __shared__ char dsm[];
    const u32 sb = smem_u32(dsm);
    __shared__ float s_sc[128], s_sb[128];

    const int tid = threadIdx.x;
    const int wid = tid >> 5, lane = tid & 31;
    const int g = lane >> 2, tg = lane & 3;
    const int wm = wid & 1, wn = wid >> 1;
    const int brow = (blockIdx.x >> 1) * 64;
    const int bcol = (blockIdx.x & 1) * 64;

    {
        const int wr = tid >> 2, wq = tid & 3;
        u32 wdst = sb + G2_WHI + (u32)wr * ROWB + (u32)wq * 64;
        const char* whi = (const char*)(Wimg + (size_t)(bcol + wr) * 128) + wq * 64;
#pragma unroll
        for (int j = 0; j < 4; j++) {
            cp16(wdst + j * 16,       whi + j * 16, 16u);
            cp16(wdst + T64 + j * 16, whi + 32768 + j * 16, 16u);
        }
        asm volatile("cp.async.commit_group;" ::: "memory");
    }
    if (PRO == 1 && tid < 128) { s_sc[tid] = scp[tid]; s_sb[tid] = sbp[tid]; }

    const int ar = tid >> 2, aq = tid & 3;
    float4 av[8];
    {
        const float4* Ap = (const float4*)(A + (size_t)(brow + ar) * CH + aq * 32);
#pragma unroll
        for (int j = 0; j < 8; j++) av[j] = Ap[j];
    }
    __syncthreads();

    {
        u64* hp = (u64*)(dsm + (u32)ar * ROWB + (u32)aq * 64);
        u64* lp = (u64*)(dsm + G2_ALO + (u32)ar * ROWB + (u32)aq * 64);
#pragma unroll
        for (int j = 0; j < 8; j++) {
            float4 v = av[j];
            if (PRO == 1) {
                int cb = aq * 32 + j * 4;
                v.x = lrelu(v.x * s_sc[cb]     + s_sb[cb]);
                v.y = lrelu(v.y * s_sc[cb + 1] + s_sb[cb + 1]);
                v.z = lrelu(v.z * s_sc[cb + 2] + s_sb[cb + 2]);
                v.w = lrelu(v.w * s_sc[cb + 3] + s_sb[cb + 3]);
            }
            __nv_bfloat162 h01 = __floats2bfloat162_rn(v.x, v.y);
            __nv_bfloat162 h23 = __floats2bfloat162_rn(v.z, v.w);
            float2 f01 = __bfloat1622float2(h01);
            float2 f23 = __bfloat1622float2(h23);
            __nv_bfloat162 l01 = __floats2bfloat162_rn(v.x - f01.x, v.y - f01.y);
            __nv_bfloat162 l23 = __floats2bfloat162_rn(v.z - f23.x, v.w - f23.y);
            hp[j] = ((u64)(*(u32*)&h23) << 32) | (u64)(*(u32*)&h01);
            lp[j] = ((u64)(*(u32*)&l23) << 32) | (u64)(*(u32*)&l01);
        }
    }
    asm volatile("cp.async.wait_group 0;" ::: "memory");
    __syncthreads();

    float acc[2][2][4];
#pragma unroll
    for (int mt = 0; mt < 2; mt++)
#pragma unroll
        for (int nt = 0; nt < 2; nt++)
#pragma unroll
            for (int q = 0; q < 4; q++) acc[mt][nt][q] = 0.f;

    mma_ld<2>(sb, sb + G2_ALO, sb + G2_WHI, sb + G2_WLO, acc, wm * 32, wn * 16, lane);

    float colS[2][2], colQ[2][2];
    if (EPI == 1) {
#pragma unroll
        for (int nt = 0; nt < 2; nt++) { colS[nt][0] = colS[nt][1] = 0.f;
                                         colQ[nt][0] = colQ[nt][1] = 0.f; }
    }

#pragma unroll
    for (int mt = 0; mt < 2; mt++) {
        int row0 = brow + wm * 32 + mt * 16 + g;
        int s0 = 0, s1 = 0;
        if (EPI == 3) { s0 = clP[row0]; s1 = clP[row0 + 8]; }
#pragma unroll
        for (int nt = 0; nt < 2; nt++) {
            int col = bcol + wn * 16 + nt * 8 + tg * 2;
            float* p0 = Cc + (size_t)row0 * CH + col;
            float* p1 = Cc + (size_t)(row0 + 8) * CH + col;
            float c0 = acc[mt][nt][0], c1 = acc[mt][nt][1];
            float c2 = acc[mt][nt][2], c3 = acc[mt][nt][3];
            if (ACC) {
                float2 o0 = *(float2*)p0, o1 = *(float2*)p1;
                c0 += o0.x; c1 += o0.y; c2 += o1.x; c3 += o1.y;
            }
            if (EPI == 3) {
                c0 = expf(c0); c1 = expf(c1); c2 = expf(c2); c3 = expf(c3);
                atomicAdd(&segEP[(size_t)s0 * CH + col],     c0);
                atomicAdd(&segEP[(size_t)s0 * CH + col + 1], c1);
                atomicAdd(&segEP[(size_t)s1 * CH + col],     c2);
                atomicAdd(&segEP[(size_t)s1 * CH + col + 1], c3);
            }
            if (EPI == 1) {
                colS[nt][0] += c0 + c2; colS[nt][1] += c1 + c3;
                colQ[nt][0] += c0 * c0 + c2 * c2; colQ[nt][1] += c1 * c1 + c3 * c3;
            }
            *(float2*)p0 = make_float2(c0, c1);
            *(float2*)p1 = make_float2(c2, c3);
        }
    }

    if (EPI == 1) {
        __syncthreads();
        float* red = (float*)dsm;
        if (tid < 128) red[tid] = 0.f;
        __syncthreads();
#pragma unroll
        for (int nt = 0; nt < 2; nt++) {
            int lc = wn * 16 + nt * 8 + tg * 2;
            atomicAdd(&red[lc],          colS[nt][0]);
            atomicAdd(&red[lc + 1],      colS[nt][1]);
            atomicAdd(&red[64 + lc],     colQ[nt][0]);
            atomicAdd(&red[64 + lc + 1], colQ[nt][1]);
        }
        __syncthreads();
        if (tid < 64) {
            atomicAdd(&sumP[bcol + tid],  red[tid]);
            atomicAdd(&sumqP[bcol + tid], red[64 + tid]);
        }
    }
}

// ====== HMMA sparse conv (128x128, A single-buffered, W double-buffered) ======
__global__ __launch_bounds__(256, 1)
void sconv_mma(const __nv_bfloat16* __restrict__ Xhi,
               const __nv_bfloat16* __restrict__ Xlo,
               const int* __restrict__ nbr,
               const __nv_bfloat16* __restrict__ Wimg,
               float* __restrict__ Out,
               float* __restrict__ sumP, float* __restrict__ sumqP)
{
    extern __shared__ char dsm[];
    const u32 sb = smem_u32(dsm);

    const int tid = threadIdx.x;
    const int wid = tid >> 5, lane = tid & 31;
    const int g = lane >> 2, tg = lane & 3;
    const int wm = wid & 3, wn = wid >> 2;
    const int brow = blockIdx.x * 128;
    const int cr = tid >> 1, chalf = tid & 1;
    const u32 rowB = (u32)cr * ROWB + (u32)chalf * 128;
    const size_t nbase = (size_t)(brow + cr) * KT;

    float acc[2][8][4];
#pragma unroll
    for (int mt = 0; mt < 2; mt++)
#pragma unroll
        for (int nt = 0; nt < 8; nt++)
#pragma unroll
            for (int q = 0; q < 4; q++) acc[mt][nt][q] = 0.f;

    auto issue_w = [&](int k, u32 wb) {
        const char* whi = (const char*)(Wimg + (size_t)k * 32768) + cr * 256 + chalf * 128;
#pragma unroll
        for (int j = 0; j < 8; j++) {
            cp16(wb + rowB + j * 16,        whi + j * 16, 16u);
            cp16(wb + T128 + rowB + j * 16, whi + 32768 + j * 16, 16u);
        }
        asm volatile("cp.async.commit_group;" ::: "memory");
    };
    auto issue_a = [&](int k) {
        int n = nbr[nbase + k];
        bool valid = n < NV;
        u32 sz = valid ? 16u : 0u;
        const char* shi = (const char*)(Xhi + (size_t)(valid ? n : 0) * CH) + chalf * 128;
        const char* slo = (const char*)(Xlo + (size_t)(valid ? n : 0) * CH) + chalf * 128;
#pragma unroll
        for (int j = 0; j < 8; j++) {
            cp16(sb + rowB + j * 16,        shi + j * 16, sz);
            cp16(sb + T128 + rowB + j * 16, slo + j * 16, sz);
        }
        asm volatile("cp.async.commit_group;" ::: "memory");
    };

    issue_w(0, sb + S_WB0);

#pragma unroll 1
    for (int k = 0; k < KT; k++) {
        const u32 wb = sb + ((k & 1) ? S_WB1 : S_WB0);
        issue_a(k);
        if (k < KT - 1) {
            issue_w(k + 1, sb + ((k & 1) ? S_WB0 : S_WB1));
            asm volatile("cp.async.wait_group 1;" ::: "memory");
        } else {
            asm volatile("cp.async.wait_group 0;" ::: "memory");
        }
        __syncthreads();

        mma_ld<8>(sb, sb + T128, wb, wb + T128, acc, wm * 32, wn * 64, lane);
        __syncthreads();
    }

    float colS[8][2], colQ[8][2];
#pragma unroll
    for (int nt = 0; nt < 8; nt++) { colS[nt][0] = colS[nt][1] = 0.f;
                                     colQ[nt][0] = colQ[nt][1] = 0.f; }
#pragma unroll
    for (int mt = 0; mt < 2; mt++) {
        int row0 = brow + wm * 32 + mt * 16 + g;
#pragma unroll
        for (int nt = 0; nt < 8; nt++) {
            int col = wn * 64 + nt * 8 + tg * 2;
            float c0 = acc[mt][nt][0], c1 = acc[mt][nt][1];
            float c2 = acc[mt][nt][2], c3 = acc[mt][nt][3];
            colS[nt][0] += c0 + c2; colS[nt][1] += c1 + c3;
            colQ[nt][0] += c0 * c0 + c2 * c2; colQ[nt][1] += c1 * c1 + c3 * c3;
            *(float2*)(Out + (size_t)row0 * CH + col)       = make_float2(c0, c1);
            *(float2*)(Out + (size_t)(row0 + 8) * CH + col) = make_float2(c2, c3);
        }
    }
    __syncthreads();
    float* red = (float*)dsm;
    if (tid < 256) red[tid] = 0.f;
    __syncthreads();
#pragma unroll
    for (int nt = 0; nt < 8; nt++) {
        int col = wn * 64 + nt * 8 + tg * 2;
        atomicAdd(&red[col],           colS[nt][0]);
        atomicAdd(&red[col + 1],       colS[nt][1]);
        atomicAdd(&red[128 + col],     colQ[nt][0]);
        atomicAdd(&red[128 + col + 1], colQ[nt][1]);
    }
    __syncthreads();
    if (tid < 128) {
        atomicAdd(&sumP[tid],  red[tid]);
        atomicAdd(&sumqP[tid], red[128 + tid]);
    }
}

// ---------------- BN finalize (self-zeroing) ----------------------------------
__global__ void bn_finalize(float* __restrict__ sum, float* __restrict__ sumsq,
                            const float* __restrict__ gamma, const float* __restrict__ beta,
                            float* __restrict__ scale, float* __restrict__ bias)
{
    int c = threadIdx.x;
    float s = sum[c], q = sumsq[c];
    sum[c] = 0.f; sumsq[c] = 0.f;
    float m = s * (1.f / (float)NV);
    float v = q * (1.f / (float)NV) - m * m;
    float sc = gamma[c] * rsqrtf(v + 1e-5f);
    scale[c] = sc;
    bias[c] = beta[c] - m * sc;
}

// ---------------- elementwise / segment kernels -------------------------------
__global__ void seg_count(const int* __restrict__ cl, float* __restrict__ cnt)
{
    int i = blockIdx.x * blockDim.x + threadIdx.x;
    atomicAdd(&cnt[cl[i]], 1.f);
}

__global__ void seg_sum_bn(float* __restrict__ X, const float* __restrict__ sc,
                           const float* __restrict__ sb, const int* __restrict__ cl,
                           float* __restrict__ S)
{
    int i = blockIdx.x * blockDim.x + threadIdx.x;
    int n = i >> 7, c = i & 127;
    float v = lrelu(X[i] * sc[c] + sb[c]);
    X[i] = v;
    atomicAdd(&S[(size_t)cl[n] * CH + c], v);
}

__global__ void sub_segmean(float* __restrict__ X, const float* __restrict__ S,
                            const float* __restrict__ cnt, const int* __restrict__ cl)
{
    int i = blockIdx.x * blockDim.x + threadIdx.x;
    int n = i >> 7, c = i & 127;
    int s = cl[n];
    X[i] -= S[(size_t)s * CH + c] / fmaxf(cnt[s], 1.f);
}

// seg2 += lrelu(bn(pf)) * T / (S + eps)   (T already holds exp values)
__global__ void wmul_seg_bn(const float* __restrict__ PF, const float* __restrict__ sc,
                            const float* __restrict__ sb, const float* __restrict__ T,
                            const float* __restrict__ S, const int* __restrict__ cl,
                            float* __restrict__ S2)
{
    int i = blockIdx.x * blockDim.x + threadIdx.x;
    int n = i >> 7, c = i & 127;
    int s = cl[n];
    float pfv = lrelu(PF[i] * sc[c] + sb[c]);
    float v = pfv * (T[i] / (S[(size_t)s * CH + c] + 1e-6f));
    atomicAdd(&S2[(size_t)s * CH + c], v);
}

// agg[n,c] = sum_lvl adp[n,lvl] * seg2[lvl][cl[lvl][n], c]
__global__ void agg_k(const float* __restrict__ adp, const int* __restrict__ clusters,
                      const float* __restrict__ S2, float* __restrict__ AGG)
{
    int i = blockIdx.x * blockDim.x + threadIdx.x;
    int n = i >> 7, c = i & 127;
    float r = 0.f;
#pragma unroll
    for (int lvl = 0; lvl < 3; lvl++) {
        int s = clusters[(size_t)lvl * NV + n];
        r += adp[n * 3 + lvl] * S2[(size_t)lvl * SEGSTRIDE + (size_t)s * CH + c];
    }
    AGG[i] = r;
}

__global__ void bnact_hilo(const float* __restrict__ X, const float* __restrict__ scale,
                           const float* __restrict__ bias,
                           __nv_bfloat16* __restrict__ Hi, __nv_bfloat16* __restrict__ Lo)
{
    int i = blockIdx.x * blockDim.x + threadIdx.x;
    int c = i & 127;
    float v = lrelu(X[i] * scale[c] + bias[c]);
    __nv_bfloat16 h = __float2bfloat16(v);
    Hi[i] = h;
    Lo[i] = __float2bfloat16(v - __bfloat162float(h));
}

__global__ void fusedres_hilo(const float* __restrict__ T, const float* __restrict__ sc,
                              const float* __restrict__ sb, const float* __restrict__ feat,
                              float* __restrict__ F,
                              __nv_bfloat16* __restrict__ Hi, __nv_bfloat16* __restrict__ Lo)
{
    int i = blockIdx.x * blockDim.x + threadIdx.x;
    int c = i & 127;
    float v = lrelu(T[i] * sc[c] + sb[c]) + feat[i];
    F[i] = v;
    __nv_bfloat16 h = __float2bfloat16(v);
    Hi[i] = h;
    Lo[i] = __float2bfloat16(v - __bfloat162float(h));
}

__global__ void final_k(const float* __restrict__ D, const float* __restrict__ sc,
                        const float* __restrict__ sb, const float* __restrict__ F,
                        float* __restrict__ O)
{
    int i = blockIdx.x * blockDim.x + threadIdx.x;
    int c = i & 127;
    O[i] = lrelu(D[i] * sc[c] + sb[c] + F[i]);
}

// ---------------- adaptive softmax -------------------------------------------
__global__ void adp_kernel(const float* __restrict__ feat, const float* __restrict__ aw,
                           float* __restrict__ adp)
{
    int row = blockIdx.x * 8 + (threadIdx.x >> 5);
    int lane = threadIdx.x & 31;
    float d0 = 0.f, d1 = 0.f, d2 = 0.f;
    const float* f = feat + (size_t)row * CH;
#pragma unroll
    for (int j = lane; j < CH; j += 32) {
        float v = f[j];
        d0 += v * aw[j * 3 + 0];
        d1 += v * aw[j * 3 + 1];
        d2 += v * aw[j * 3 + 2];
    }
#pragma unroll
    for (int o = 16; o; o >>= 1) {
        d0 += __shfl_xor_sync(0xffffffffu, d0, o);
        d1 += __shfl_xor_sync(0xffffffffu, d1, o);
        d2 += __shfl_xor_sync(0xffffffffu, d2, o);
    }
    if (lane == 0) {
        float m = fmaxf(d0, fmaxf(d1, d2));
        float e0 = expf(d0 - m), e1 = expf(d1 - m), e2 = expf(d2 - m);
        float inv = 1.f / (e0 + e1 + e2);
        adp[row * 3 + 0] = e0 * inv;
        adp[row * 3 + 1] = e1 * inv;
        adp[row * 3 + 2] = e2 * inv;
    }
}

// ---------------- orchestration ----------------------------------------------
extern "C" void kernel_launch(void* const* d_in, const int* in_sizes, int n_in,
                              void* d_out, int out_size)
{
    const float* feat       = (const float*)d_in[0];
    const int*   clusters   = (const int*)d_in[1];
    const int*   nbr        = (const int*)d_in[2];
    const float* lw_w       = (const float*)d_in[3];
    const float* lw_gamma   = (const float*)d_in[4];
    const float* lw_beta    = (const float*)d_in[5];
    const float* w_w        = (const float*)d_in[6];
    const float* proj_w     = (const float*)d_in[7];
    const float* proj_gamma = (const float*)d_in[8];
    const float* proj_beta  = (const float*)d_in[9];
    const float* adaptive_w = (const float*)d_in[10];
    const float* fuse_w     = (const float*)d_in[11];
    const float* fuse_gamma = (const float*)d_in[12];
    const float* fuse_beta  = (const float*)d_in[13];
    const float* conv1_w    = (const float*)d_in[14];
    const float* conv2_w    = (const float*)d_in[15];
    const float* bn1_gamma  = (const float*)d_in[16];
    const float* bn1_beta   = (const float*)d_in[17];
    const float* bn2_gamma  = (const float*)d_in[18];
    const float* bn2_beta   = (const float*)d_in[19];
    float* out = (float*)d_out;

    float *pw3, *t3, *pf4, *tf, *agg, *fused, *ybuf, *dbuf, *adp;
    float *segall, *cnt3, *sum8, *sumq8, *scale8, *bias8;
    __nv_bfloat16 *wimg, *dwimg, *xhi, *xlo;
    cudaGetSymbolAddress((void**)&pw3, g_pw3);
    cudaGetSymbolAddress((void**)&t3, g_t3);
    cudaGetSymbolAddress((void**)&pf4, g_pf4);
    cudaGetSymbolAddress((void**)&tf, g_tf);
    cudaGetSymbolAddress((void**)&agg, g_agg);
    cudaGetSymbolAddress((void**)&fused, g_fused);
    cudaGetSymbolAddress((void**)&ybuf, g_ybuf);
    cudaGetSymbolAddress((void**)&dbuf, g_dbuf);
    cudaGetSymbolAddress((void**)&adp, g_adp);
    cudaGetSymbolAddress((void**)&segall, g_segall);
    cudaGetSymbolAddress((void**)&cnt3, g_cnt3);
    cudaGetSymbolAddress((void**)&sum8, g_sum8);
    cudaGetSymbolAddress((void**)&sumq8, g_sumq8);
    cudaGetSymbolAddress((void**)&scale8, g_scale8);
    cudaGetSymbolAddress((void**)&bias8, g_bias8);
    cudaGetSymbolAddress((void**)&wimg, g_wimg);
    cudaGetSymbolAddress((void**)&dwimg, g_dwimg);
    cudaGetSymbolAddress((void**)&xhi, g_xhi);
    cudaGetSymbolAddress((void**)&xlo, g_xlo);

    cudaFuncSetAttribute(sconv_mma, cudaFuncAttributeMaxDynamicSharedMemorySize, SSMEM);
    cudaFuncSetAttribute(gemm_mma<0,1,0>, cudaFuncAttributeMaxDynamicSharedMemorySize, GSMEM2);
    cudaFuncSetAttribute(gemm_mma<0,3,0>, cudaFuncAttributeMaxDynamicSharedMemorySize, GSMEM2);
    cudaFuncSetAttribute(gemm_mma<1,0,0>, cudaFuncAttributeMaxDynamicSharedMemorySize, GSMEM2);
    cudaFuncSetAttribute(gemm_mma<0,1,1>, cudaFuncAttributeMaxDynamicSharedMemorySize, GSMEM2);

    static cudaStream_t st[3];
    static cudaEvent_t evR, evJ[3];
    static int inited = 0;
    if (!inited) {
        for (int k = 0; k < 3; k++)
            cudaStreamCreateWithFlags(&st[k], cudaStreamNonBlocking);
        cudaEventCreateWithFlags(&evR, cudaEventDisableTiming);
        for (int k = 0; k < 3; k++)
            cudaEventCreateWithFlags(&evJ[k], cudaEventDisableTiming);
        inited = 1;
    }

    const int EB = 256;
    const int EG = NC / EB;
    const int GG2 = (NV / 64) * 2;

    // ---- prologue ----
    wprep<<<2 * KT, 256>>>(conv1_w, conv2_w, wimg);
    dwprep<<<12, 256>>>(lw_w, w_w, proj_w, fuse_w, dwimg);
    adp_kernel<<<NV / 8, 256>>>(feat, adaptive_w, adp);

    // ---- fork ----
    cudaEventRecord(evR, 0);
    for (int k = 0; k < 3; k++) cudaStreamWaitEvent(st[k], evR, 0);

    auto level_chain = [&](int i, cudaStream_t s) {
        const int* cl = clusters + (size_t)i * NV;
        float* pw = pw3 + (size_t)i * NC;
        float* t  = t3  + (size_t)i * NC;
        float* pf = pf4 + (size_t)i * NC;
        float* segbase = segall + (size_t)i * SEGSTRIDE;
        float* seg  = segbase;
        float* sgE  = segbase + SEGS;
        float* sg2  = segbase + 2 * SEGS;
        float* cnt  = cnt3 + (size_t)i * NSEGS;
        float* sum  = sum8 + i * CH;
        float* sumq = sumq8 + i * CH;
        float* sc   = scale8 + i * CH;
        float* sb   = bias8 + i * CH;

        cudaMemsetAsync(segbase, 0, (size_t)SEGSTRIDE * sizeof(float), s);
        cudaMemsetAsync(cnt, 0, NSEGS * sizeof(float), s);
        seg_count<<<NV / 256, 256, 0, s>>>(cl, cnt);
        gemm_mma<0,1,0><<<GG2, 256, GSMEM2, s>>>(feat, dwimg + (size_t)i * 32768, pw,
                                                 nullptr, nullptr, sum, sumq,
                                                 nullptr, nullptr);
        bn_finalize<<<1, 128, 0, s>>>(sum, sumq, lw_gamma + i * CH, lw_beta + i * CH, sc, sb);
        seg_sum_bn<<<EG, EB, 0, s>>>(pw, sc, sb, cl, seg);
        sub_segmean<<<EG, EB, 0, s>>>(pw, seg, cnt, cl);
        // t = exp(pw @ w_w[i]) with in-epilogue segment sum into sgE
        gemm_mma<0,3,0><<<GG2, 256, GSMEM2, s>>>(pw, dwimg + (size_t)(3 + i) * 32768, t,
                                                 nullptr, nullptr, nullptr, nullptr,
                                                 cl, sgE);
        gemm_mma<0,1,0><<<GG2, 256, GSMEM2, s>>>(feat, dwimg + (size_t)(6 + i) * 32768, pf,
                                                 nullptr, nullptr, sum, sumq,
                                                 nullptr, nullptr);
        bn_finalize<<<1, 128, 0, s>>>(sum, sumq, proj_gamma + i * CH, proj_beta + i * CH, sc, sb);
        wmul_seg_bn<<<EG, EB, 0, s>>>(pf, sc, sb, t, sgE, cl, sg2);
    };

    level_chain(0, 0);
    level_chain(1, st[0]);
    level_chain(2, st[1]);

    {
        cudaStream_t s = st[2];
        float* pf3 = pf4 + (size_t)3 * NC;
        float* sum  = sum8 + 3 * CH;
        float* sumq = sumq8 + 3 * CH;
        float* sc   = scale8 + 3 * CH;
        float* sb   = bias8 + 3 * CH;
        gemm_mma<0,1,0><<<GG2, 256, GSMEM2, s>>>(feat, dwimg + (size_t)9 * 32768, pf3,
                                                 nullptr, nullptr, sum, sumq,
                                                 nullptr, nullptr);
        bn_finalize<<<1, 128, 0, s>>>(sum, sumq, proj_gamma + 3 * CH, proj_beta + 3 * CH, sc, sb);
        gemm_mma<1,0,0><<<GG2, 256, GSMEM2, s>>>(pf3, dwimg + (size_t)10 * 32768, tf,
                                                 sc, sb, nullptr, nullptr,
                                                 nullptr, nullptr);
    }

    // ---- join ----
    for (int k = 0; k < 3; k++) cudaEventRecord(evJ[k], st[k]);
    for (int k = 0; k < 3; k++) cudaStreamWaitEvent(0, evJ[k], 0);

    // ---- epilogue ----
    float* sumF  = sum8 + 4 * CH;
    float* sumqF = sumq8 + 4 * CH;
    float* scF   = scale8 + 4 * CH;
    float* sbF   = bias8 + 4 * CH;

    agg_k<<<EG, EB>>>(adp, clusters, segall + 2 * SEGS, agg);
    gemm_mma<0,1,1><<<GG2, 256, GSMEM2>>>(agg, dwimg + (size_t)11 * 32768, tf,
                                          nullptr, nullptr, sumF, sumqF,
                                          nullptr, nullptr);
    bn_finalize<<<1, 128>>>(sumF, sumqF, fuse_gamma, fuse_beta, scF, sbF);
    fusedres_hilo<<<EG, EB>>>(tf, scF, sbF, feat, fused, xhi, xlo);

    sconv_mma<<<512, 256, SSMEM>>>(xhi, xlo, nbr, wimg, ybuf, sumF, sumqF);
    bn_finalize<<<1, 128>>>(sumF, sumqF, bn1_gamma, bn1_beta, scF, sbF);
    bnact_hilo<<<EG, EB>>>(ybuf, scF, sbF, xhi, xlo);

    sconv_mma<<<512, 256, SSMEM>>>(xhi, xlo, nbr, wimg + (size_t)KT * 32768, dbuf, sumF, sumqF);
    bn_finalize<<<1, 128>>>(sumF, sumqF, bn2_gamma, bn2_beta, scF, sbF);
    final_k<<<EG, EB>>>(dbuf, scF, sbF, fused, out);
}